// round 4
// baseline (speedup 1.0000x reference)
#include <cuda_runtime.h>
#include <math.h>
#include <mma.h>

using namespace nvcuda;

#define Bn   32
#define Sn   1024
#define En   128
#define Hn   512
#define Gn   2048
#define Mn   32768
#define NBLK 128

#define TFS_LD     20
#define SCRATCH_LD 72
#define GEMM_SMEM  (8 * 32 * SCRATCH_LD * 4)   // 73728 B (aliases the 20KB stage area)

__device__ float g_embed[Mn * En];
__device__ float g_a1[Mn * En];
__device__ float g_a[Mn * 3];
__device__ float g_attn[Mn * 3];
__device__ float g_xproj[(size_t)Mn * Gn];
__device__ float g_enc[(size_t)Mn * Hn];
__device__ float g_ctx[(size_t)Mn * Hn];
__device__ float g_pred[Mn];
__device__ float g_h[2 * Bn * Hn];
__device__ unsigned g_bar_cnt;
__device__ unsigned g_bar_rel;

__device__ __forceinline__ void grid_bar(unsigned phase) {
    __syncthreads();
    if (threadIdx.x == 0) {
        __threadfence();
        unsigned v = atomicAdd(&g_bar_cnt, 1u);
        if (v == phase * (unsigned)NBLK + (unsigned)(NBLK - 1)) {
            __threadfence();
            *(volatile unsigned*)&g_bar_rel = phase + 1u;
        } else {
            while (*(volatile unsigned*)&g_bar_rel < phase + 1u) { __nanosleep(64); }
        }
    }
    __syncthreads();
    __threadfence();
}

__device__ __forceinline__ float sigmoidf_(float x) { return 1.0f / (1.0f + expf(-x)); }

// ---------------------------------------------------------------------------
// 3xTF32 tensor-core GEMM: C[M,N] = act(A[M,K] @ B[N,K]^T + bias1 + bias2)
// B row-stride ldb, column offset koff. 128x128 tile, BK=16, 8 warps (4x2).
// Error-compensated: A=A_hi+A_lo, B=B_hi+B_lo, acc += hi*hi + hi*lo + lo*hi.
// ---------------------------------------------------------------------------
__global__ void __launch_bounds__(256, 1) tf32_gemm_kernel(
    const float* __restrict__ A, const float* __restrict__ B, float* __restrict__ C,
    int M, int N, int K, int lda, int ldb, int koff,
    const float* __restrict__ bias1, const float* __restrict__ bias2, int relu)
{
    extern __shared__ float smg[];
    float* As = smg;                   // [128][20]
    float* Bs = smg + 128 * TFS_LD;    // [128][20]

    const int tid = threadIdx.x;
    const int wid = tid >> 5;
    const int lane = tid & 31;
    const int bx = blockIdx.x, by = blockIdx.y;
    const int warp_m = wid >> 1;       // 0..3
    const int warp_n = wid & 1;        // 0..1

    wmma::fragment<wmma::accumulator, 16, 16, 8, float> acc[2][4];
    #pragma unroll
    for (int mi = 0; mi < 2; ++mi)
        #pragma unroll
        for (int ni = 0; ni < 4; ++ni) wmma::fill_fragment(acc[mi][ni], 0.f);

    const int r  = tid >> 1;
    const int cp = (tid & 1) * 8;
    const float* Ag = A + (size_t)(by * 128 + r) * lda + cp;
    const float* Bg = B + (size_t)(bx * 128 + r) * ldb + koff + cp;
    float* as = As + r * TFS_LD + cp;
    float* bs = Bs + r * TFS_LD + cp;

    for (int k0 = 0; k0 < K; k0 += 16) {
        float4 av0 = *(const float4*)(Ag + k0);
        float4 av1 = *(const float4*)(Ag + k0 + 4);
        as[0] = av0.x; as[1] = av0.y; as[2] = av0.z; as[3] = av0.w;
        as[4] = av1.x; as[5] = av1.y; as[6] = av1.z; as[7] = av1.w;
        #pragma unroll
        for (int i = 0; i < 8; ++i) bs[i] = Bg[k0 + i];
        __syncthreads();

        #pragma unroll
        for (int ks = 0; ks < 16; ks += 8) {
            wmma::fragment<wmma::matrix_a, 16, 16, 8, wmma::precision::tf32, wmma::row_major> a_hi[2], a_lo[2];
            wmma::fragment<wmma::matrix_b, 16, 16, 8, wmma::precision::tf32, wmma::col_major> b_hi[4], b_lo[4];
            #pragma unroll
            for (int mi = 0; mi < 2; ++mi) {
                wmma::load_matrix_sync(a_lo[mi], As + (warp_m * 32 + mi * 16) * TFS_LD + ks, TFS_LD);
                #pragma unroll
                for (int e = 0; e < a_lo[mi].num_elements; ++e) {
                    float raw = a_lo[mi].x[e];
                    float hi  = wmma::__float_to_tf32(raw);
                    a_hi[mi].x[e] = hi;
                    a_lo[mi].x[e] = wmma::__float_to_tf32(raw - hi);
                }
            }
            #pragma unroll
            for (int ni = 0; ni < 4; ++ni) {
                wmma::load_matrix_sync(b_lo[ni], Bs + (warp_n * 64 + ni * 16) * TFS_LD + ks, TFS_LD);
                #pragma unroll
                for (int e = 0; e < b_lo[ni].num_elements; ++e) {
                    float raw = b_lo[ni].x[e];
                    float hi  = wmma::__float_to_tf32(raw);
                    b_hi[ni].x[e] = hi;
                    b_lo[ni].x[e] = wmma::__float_to_tf32(raw - hi);
                }
            }
            #pragma unroll
            for (int mi = 0; mi < 2; ++mi)
                #pragma unroll
                for (int ni = 0; ni < 4; ++ni) {
                    wmma::mma_sync(acc[mi][ni], a_hi[mi], b_hi[ni], acc[mi][ni]);
                    wmma::mma_sync(acc[mi][ni], a_hi[mi], b_lo[ni], acc[mi][ni]);
                    wmma::mma_sync(acc[mi][ni], a_lo[mi], b_hi[ni], acc[mi][ni]);
                }
        }
        __syncthreads();
    }

    // epilogue: per-warp smem scratch (aliases stage area; all reads done)
    float* scr = smg + wid * (32 * SCRATCH_LD);
    #pragma unroll
    for (int mi = 0; mi < 2; ++mi)
        #pragma unroll
        for (int ni = 0; ni < 4; ++ni)
            wmma::store_matrix_sync(scr + mi * 16 * SCRATCH_LD + ni * 16,
                                    acc[mi][ni], SCRATCH_LD, wmma::mem_row_major);
    __syncwarp();

    const int m_base = by * 128 + warp_m * 32;
    const int n_base = bx * 128 + warp_n * 64;
    #pragma unroll 4
    for (int i = 0; i < 64; ++i) {
        int idx = i * 32 + lane;
        int rr = idx >> 6, cc = idx & 63;
        float v = scr[rr * SCRATCH_LD + cc];
        int n = n_base + cc;
        if (bias1) v += bias1[n];
        if (bias2) v += bias2[n];
        if (relu)  v = fmaxf(v, 0.f);
        C[(size_t)(m_base + rr) * N + n] = v;
    }
}

__global__ void attn_logits_kernel(const float* __restrict__ a1,
                                   const float* __restrict__ W_a2,
                                   const float* __restrict__ b_a2,
                                   float* __restrict__ a)
{
    int gw = (blockIdx.x * blockDim.x + threadIdx.x) >> 5;
    int lane = threadIdx.x & 31;
    if (gw >= Mn) return;
    float4 v = ((const float4*)(a1 + (size_t)gw * En))[lane];
    #pragma unroll
    for (int l = 0; l < 3; ++l) {
        float4 wv = ((const float4*)(W_a2 + l * En))[lane];
        float s = v.x * wv.x + v.y * wv.y + v.z * wv.z + v.w * wv.w;
        #pragma unroll
        for (int o = 16; o; o >>= 1) s += __shfl_xor_sync(0xffffffffu, s, o);
        if (lane == 0) a[(size_t)gw * 3 + l] = s + b_a2[l];
    }
}

__global__ void softmax_time_kernel(const float* __restrict__ a, float* __restrict__ attn)
{
    __shared__ float red[256];
    int b = blockIdx.x / 3, l = blockIdx.x - b * 3;
    const float* base = a + (size_t)b * Sn * 3 + l;
    float mx = -3.4e38f;
    for (int s = threadIdx.x; s < Sn; s += 256) mx = fmaxf(mx, base[(size_t)s * 3]);
    red[threadIdx.x] = mx; __syncthreads();
    for (int o = 128; o; o >>= 1) {
        if (threadIdx.x < o) red[threadIdx.x] = fmaxf(red[threadIdx.x], red[threadIdx.x + o]);
        __syncthreads();
    }
    mx = red[0]; __syncthreads();
    float sum = 0.f;
    for (int s = threadIdx.x; s < Sn; s += 256) sum += expf(base[(size_t)s * 3] - mx);
    red[threadIdx.x] = sum; __syncthreads();
    for (int o = 128; o; o >>= 1) {
        if (threadIdx.x < o) red[threadIdx.x] += red[threadIdx.x + o];
        __syncthreads();
    }
    float inv = 1.f / red[0];
    float* ob = attn + (size_t)b * Sn * 3 + l;
    for (int s = threadIdx.x; s < Sn; s += 256)
        ob[(size_t)s * 3] = expf(base[(size_t)s * 3] - mx) * inv;
}

__global__ void context_kernel(const float* __restrict__ attn,
                               const float* __restrict__ enc,
                               float* __restrict__ ctx)
{
    int m = blockIdx.x;
    int t = m & (Sn - 1);
    float a0 = attn[(size_t)m * 3 + 0];
    float a1 = attn[(size_t)m * 3 + 1];
    float a2 = attn[(size_t)m * 3 + 2];
    float4 e0 = ((const float4*)(enc + (size_t)m * Hn))[threadIdx.x];
    float4 r; r.x = a0 * e0.x; r.y = a0 * e0.y; r.z = a0 * e0.z; r.w = a0 * e0.w;
    if (t >= 1) {
        float4 e1 = ((const float4*)(enc + (size_t)(m - 1) * Hn))[threadIdx.x];
        r.x += a1 * e1.x; r.y += a1 * e1.y; r.z += a1 * e1.z; r.w += a1 * e1.w;
    }
    if (t >= 2) {
        float4 e2 = ((const float4*)(enc + (size_t)(m - 2) * Hn))[threadIdx.x];
        r.x += a2 * e2.x; r.y += a2 * e2.y; r.z += a2 * e2.z; r.w += a2 * e2.w;
    }
    ((float4*)(ctx + (size_t)m * Hn))[threadIdx.x] = r;
}

__global__ void init_enc_kernel(const float* __restrict__ h0)
{
    int i = blockIdx.x * 256 + threadIdx.x;
    if (i < Bn * Hn) g_h[i] = h0[i & (Hn - 1)];
    if (i == 0) { g_bar_cnt = 0u; *(volatile unsigned*)&g_bar_rel = 0u; }
}

__global__ void init_dec_kernel(const float* __restrict__ h0, const float* __restrict__ b_o2)
{
    int i = blockIdx.x * 256 + threadIdx.x;
    if (i < Bn * Hn) g_h[i] = h0[i & (Hn - 1)];
    if (i < Mn) g_pred[i] = b_o2[0];
    if (i == 0) { g_bar_cnt = 0u; *(volatile unsigned*)&g_bar_rel = 0u; }
}

#define ENC_SMEM ((16 * 512 + 32 * 516 + 128 * 4) * 4)
__global__ void __launch_bounds__(256, 1) lstm_enc_kernel(
    const float* __restrict__ xproj, const float* __restrict__ Whh,
    const float* __restrict__ c0, const int* __restrict__ lengths,
    float* __restrict__ enc_out)
{
    extern __shared__ float sm[];
    float* w_s   = sm;
    float* h_s   = sm + 16 * 512;
    float* red_s = h_s + 32 * 516;

    const int bl = blockIdx.x, tid = threadIdx.x;
    const int half = tid >> 7, tl = tid & 127;
    const int b = tl & 31, jj = tl >> 5;
    const int j = bl * 4 + jj;

    for (int i = tid; i < 16 * 512; i += 256) {
        int lr = i >> 9, k = i & 511;
        int g = lr >> 2, j2 = lr & 3;
        w_s[i] = Whh[(size_t)(g * Hn + bl * 4 + j2) * Hn + k];
    }
    float c_reg = (half == 0) ? c0[j] : 0.f;
    const int len_b = lengths[b];
    __syncthreads();

    const float4* w0 = (const float4*)(w_s + (0 * 4 + jj) * 512);
    const float4* w1 = (const float4*)(w_s + (1 * 4 + jj) * 512);
    const float4* w2 = (const float4*)(w_s + (2 * 4 + jj) * 512);
    const float4* w3 = (const float4*)(w_s + (3 * 4 + jj) * 512);
    const float4* hv = (const float4*)(h_s + b * 516);
    const int kbeg = half * 64, kend = kbeg + 64;

    for (int t = 0; t < Sn; ++t) {
        const float4* src = (const float4*)(g_h + (t & 1) * (Bn * Hn));
        #pragma unroll
        for (int i = 0; i < 16; ++i) {
            int idx = tid + i * 256;
            float4 v = __ldcg(src + idx);
            ((float4*)(h_s + (idx >> 7) * 516))[idx & 127] = v;
        }
        __syncthreads();

        float a0 = 0.f, a1 = 0.f, a2 = 0.f, a3 = 0.f;
        #pragma unroll 8
        for (int kk = kbeg; kk < kend; ++kk) {
            float4 h4 = hv[kk]; float4 v;
            v = w0[kk]; a0 += h4.x * v.x + h4.y * v.y + h4.z * v.z + h4.w * v.w;
            v = w1[kk]; a1 += h4.x * v.x + h4.y * v.y + h4.z * v.z + h4.w * v.w;
            v = w2[kk]; a2 += h4.x * v.x + h4.y * v.y + h4.z * v.z + h4.w * v.w;
            v = w3[kk]; a3 += h4.x * v.x + h4.y * v.y + h4.z * v.z + h4.w * v.w;
        }
        if (half == 1) {
            float* r = red_s + tl * 4;
            r[0] = a0; r[1] = a1; r[2] = a2; r[3] = a3;
        }
        __syncthreads();
        if (half == 0) {
            const float* r  = red_s + tl * 4;
            const float* xp = xproj + (size_t)(b * Sn + t) * Gn + j;
            float gi = a0 + r[0] + xp[0 * Hn];
            float gf = a1 + r[1] + xp[1 * Hn];
            float gg = a2 + r[2] + xp[2 * Hn];
            float go = a3 + r[3] + xp[3 * Hn];
            float si = sigmoidf_(gi), sf = sigmoidf_(gf), so = sigmoidf_(go);
            c_reg = sf * c_reg + si * tanhf(gg);
            float hh = so * tanhf(c_reg);
            __stcg(&g_h[((t + 1) & 1) * (Bn * Hn) + b * Hn + j], hh);
            enc_out[(size_t)(b * Sn + t) * Hn + j] = (t < len_b) ? hh : 0.f;
        }
        grid_bar((unsigned)t);
    }
}

#define DEC_SMEM ((16 * 512 + 32 * 516 + 128 * 4 + 512 + 16) * 4)
__global__ void __launch_bounds__(256, 1) lstm_dec_kernel(
    const float* __restrict__ ctxproj, const float* __restrict__ Whh,
    const float* __restrict__ Wih, const float* __restrict__ c0,
    const float* __restrict__ W_o1, const float* __restrict__ b_o1,
    const float* __restrict__ W_o2)
{
    extern __shared__ float sm[];
    float* w_s   = sm;
    float* h_s   = sm + 16 * 512;
    float* red_s = h_s + 32 * 516;
    float* wo1_s = red_s + 512;
    float* wp_s  = wo1_s + 512;

    const int bl = blockIdx.x, tid = threadIdx.x;
    const int half = tid >> 7, tl = tid & 127;
    const int b = tl & 31, jj = tl >> 5;
    const int j = bl * 4 + jj;

    for (int i = tid; i < 16 * 512; i += 256) {
        int lr = i >> 9, k = i & 511;
        int g = lr >> 2, j2 = lr & 3;
        w_s[i] = Whh[(size_t)(g * Hn + bl * 4 + j2) * Hn + k];
    }
    for (int i = tid; i < 512; i += 256) wo1_s[i] = W_o1[(size_t)bl * Hn + i];
    if (tid < 16) {
        int g = tid >> 2, j2 = tid & 3;
        wp_s[tid] = Wih[(size_t)(g * Hn + bl * 4 + j2) * 513];
    }
    const float wo2 = W_o2[bl];
    const float bo1 = b_o1[bl];
    float c_reg = (half == 0) ? c0[j] : 0.f;
    __syncthreads();

    const float4* w0 = (const float4*)(w_s + (0 * 4 + jj) * 512);
    const float4* w1 = (const float4*)(w_s + (1 * 4 + jj) * 512);
    const float4* w2 = (const float4*)(w_s + (2 * 4 + jj) * 512);
    const float4* w3 = (const float4*)(w_s + (3 * 4 + jj) * 512);
    const float4* hv = (const float4*)(h_s + b * 516);
    const int kbeg = half * 64, kend = kbeg + 64;
    const int warp = tid >> 5, lane = tid & 31;

    for (int t = 0; t < Sn; ++t) {
        const float4* src = (const float4*)(g_h + (t & 1) * (Bn * Hn));
        #pragma unroll
        for (int i = 0; i < 16; ++i) {
            int idx = tid + i * 256;
            float4 v = __ldcg(src + idx);
            ((float4*)(h_s + (idx >> 7) * 516))[idx & 127] = v;
        }
        __syncthreads();

        if (t > 0) {
            #pragma unroll
            for (int bi = 0; bi < 4; ++bi) {
                int bb = warp * 4 + bi;
                float s = 0.f;
                #pragma unroll
                for (int kk = 0; kk < 16; ++kk) {
                    int k = kk * 32 + lane;
                    s += wo1_s[k] * h_s[bb * 516 + k];
                }
                #pragma unroll
                for (int o = 16; o; o >>= 1) s += __shfl_xor_sync(0xffffffffu, s, o);
                if (lane == 0) {
                    float o1 = fmaxf(s + bo1, 0.f);
                    atomicAdd(&g_pred[bb * Sn + (t - 1)], o1 * wo2);
                }
            }
        }
        grid_bar(2u * (unsigned)t);

        float a0 = 0.f, a1 = 0.f, a2 = 0.f, a3 = 0.f;
        #pragma unroll 8
        for (int kk = kbeg; kk < kend; ++kk) {
            float4 h4 = hv[kk]; float4 v;
            v = w0[kk]; a0 += h4.x * v.x + h4.y * v.y + h4.z * v.z + h4.w * v.w;
            v = w1[kk]; a1 += h4.x * v.x + h4.y * v.y + h4.z * v.z + h4.w * v.w;
            v = w2[kk]; a2 += h4.x * v.x + h4.y * v.y + h4.z * v.z + h4.w * v.w;
            v = w3[kk]; a3 += h4.x * v.x + h4.y * v.y + h4.z * v.z + h4.w * v.w;
        }
        if (half == 1) {
            float* r = red_s + tl * 4;
            r[0] = a0; r[1] = a1; r[2] = a2; r[3] = a3;
        }
        __syncthreads();
        if (half == 0) {
            float p_prev = (t > 0) ? __ldcg(&g_pred[b * Sn + (t - 1)]) : 0.f;
            const float* r  = red_s + tl * 4;
            const float* xp = ctxproj + (size_t)(b * Sn + t) * Gn + j;
            float gi = a0 + r[0] + xp[0 * Hn] + p_prev * wp_s[0 * 4 + jj];
            float gf = a1 + r[1] + xp[1 * Hn] + p_prev * wp_s[1 * 4 + jj];
            float gg = a2 + r[2] + xp[2 * Hn] + p_prev * wp_s[2 * 4 + jj];
            float go = a3 + r[3] + xp[3 * Hn] + p_prev * wp_s[3 * 4 + jj];
            float si = sigmoidf_(gi), sf = sigmoidf_(gf), so = sigmoidf_(go);
            c_reg = sf * c_reg + si * tanhf(gg);
            float hh = so * tanhf(c_reg);
            __stcg(&g_h[((t + 1) & 1) * (Bn * Hn) + b * Hn + j], hh);
        }
        grid_bar(2u * (unsigned)t + 1u);
    }

    {
        const float4* src = (const float4*)(g_h + (Sn & 1) * (Bn * Hn));
        #pragma unroll
        for (int i = 0; i < 16; ++i) {
            int idx = tid + i * 256;
            float4 v = __ldcg(src + idx);
            ((float4*)(h_s + (idx >> 7) * 516))[idx & 127] = v;
        }
        __syncthreads();
        #pragma unroll
        for (int bi = 0; bi < 4; ++bi) {
            int bb = warp * 4 + bi;
            float s = 0.f;
            #pragma unroll
            for (int kk = 0; kk < 16; ++kk) {
                int k = kk * 32 + lane;
                s += wo1_s[k] * h_s[bb * 516 + k];
            }
            #pragma unroll
            for (int o = 16; o; o >>= 1) s += __shfl_xor_sync(0xffffffffu, s, o);
            if (lane == 0) {
                float o1 = fmaxf(s + bo1, 0.f);
                atomicAdd(&g_pred[bb * Sn + (Sn - 1)], o1 * wo2);
            }
        }
    }
}

__global__ void finalize_kernel(const float* __restrict__ mask, float* __restrict__ out)
{
    int i = blockIdx.x * 256 + threadIdx.x;
    if (i < Mn) out[i] = g_pred[i] * mask[i];
}

extern "C" void kernel_launch(void* const* d_in, const int* in_sizes, int n_in,
                              void* d_out, int out_size)
{
    const float* inputs  = (const float*)d_in[0];
    const float* mask    = (const float*)d_in[1];
    const int*   lengths = (const int*)  d_in[2];
    const float* W_e     = (const float*)d_in[3];
    const float* b_e     = (const float*)d_in[4];
    const float* W_a1    = (const float*)d_in[5];
    const float* b_a1    = (const float*)d_in[6];
    const float* W_a2    = (const float*)d_in[7];
    const float* b_a2    = (const float*)d_in[8];
    const float* Wih_e   = (const float*)d_in[9];
    const float* Whh_e   = (const float*)d_in[10];
    const float* bih_e   = (const float*)d_in[11];
    const float* bhh_e   = (const float*)d_in[12];
    const float* enc_h0  = (const float*)d_in[13];
    const float* enc_c0  = (const float*)d_in[14];
    const float* Wih_d   = (const float*)d_in[15];
    const float* Whh_d   = (const float*)d_in[16];
    const float* bih_d   = (const float*)d_in[17];
    const float* bhh_d   = (const float*)d_in[18];
    const float* dec_h0  = (const float*)d_in[19];
    const float* dec_c0  = (const float*)d_in[20];
    const float* W_o1    = (const float*)d_in[21];
    const float* b_o1    = (const float*)d_in[22];
    const float* W_o2    = (const float*)d_in[23];
    const float* b_o2    = (const float*)d_in[24];
    float* out = (float*)d_out;

    float *p_embed, *p_a1, *p_a, *p_attn, *p_xproj, *p_enc, *p_ctx;
    cudaGetSymbolAddress((void**)&p_embed, g_embed);
    cudaGetSymbolAddress((void**)&p_a1,    g_a1);
    cudaGetSymbolAddress((void**)&p_a,     g_a);
    cudaGetSymbolAddress((void**)&p_attn,  g_attn);
    cudaGetSymbolAddress((void**)&p_xproj, g_xproj);
    cudaGetSymbolAddress((void**)&p_enc,   g_enc);
    cudaGetSymbolAddress((void**)&p_ctx,   g_ctx);

    cudaFuncSetAttribute(tf32_gemm_kernel, cudaFuncAttributeMaxDynamicSharedMemorySize, GEMM_SMEM);
    cudaFuncSetAttribute(lstm_enc_kernel, cudaFuncAttributeMaxDynamicSharedMemorySize, ENC_SMEM);
    cudaFuncSetAttribute(lstm_dec_kernel, cudaFuncAttributeMaxDynamicSharedMemorySize, DEC_SMEM);

    // 1) embed = relu(inputs @ W_e^T + b_e)   (32768 x 128, K=1024)
    tf32_gemm_kernel<<<dim3(En / 128, Mn / 128), 256, GEMM_SMEM>>>(
        inputs, W_e, p_embed, Mn, En, 1024, 1024, 1024, 0, b_e, nullptr, 1);
    // 2) a1 = relu(embed @ W_a1^T + b_a1)     (32768 x 128, K=128)
    tf32_gemm_kernel<<<dim3(En / 128, Mn / 128), 256, GEMM_SMEM>>>(
        p_embed, W_a1, p_a1, Mn, En, En, En, En, 0, b_a1, nullptr, 1);
    // 3) attention logits + softmax over time
    attn_logits_kernel<<<Mn / 8, 256>>>(p_a1, W_a2, b_a2, p_a);
    softmax_time_kernel<<<Bn * 3, 256>>>(p_a, p_attn);
    // 4) encoder input projection (32768 x 2048, K=128)
    tf32_gemm_kernel<<<dim3(Gn / 128, Mn / 128), 256, GEMM_SMEM>>>(
        p_embed, Wih_e, p_xproj, Mn, Gn, En, En, En, 0, bih_e, bhh_e, 0);
    // 5) encoder LSTM (persistent)
    init_enc_kernel<<<(Bn * Hn + 255) / 256, 256>>>(enc_h0);
    lstm_enc_kernel<<<NBLK, 256, ENC_SMEM>>>(p_xproj, Whh_e, enc_c0, lengths, p_enc);
    // 6) context conv
    context_kernel<<<Mn, Hn / 4>>>(p_attn, p_enc, p_ctx);
    // 7) decoder ctx projection (32768 x 2048, K=512), Wih_d cols 1..512
    tf32_gemm_kernel<<<dim3(Gn / 128, Mn / 128), 256, GEMM_SMEM>>>(
        p_ctx, Wih_d, p_xproj, Mn, Gn, Hn, Hn, Hn + 1, 1, bih_d, bhh_d, 0);
    // 8) decoder LSTM (persistent) + output MLP
    init_dec_kernel<<<(Mn + 255) / 256, 256>>>(dec_h0, b_o2);
    lstm_dec_kernel<<<NBLK, 256, DEC_SMEM>>>(p_xproj, Whh_d, Wih_d, dec_c0, W_o1, b_o1, W_o2);
    // 9) out = pred * mask
    finalize_kernel<<<(Mn + 255) / 256, 256>>>(mask, out);
}

// round 5
// speedup vs baseline: 1.1266x; 1.1266x over previous
#include <cuda_runtime.h>
#include <math.h>

#define Bn   32
#define Sn   1024
#define En   128
#define Hn   512
#define Gn   2048
#define Mn   32768
#define NBLK 128

__device__ float g_embed[Mn * En];
__device__ float g_a1[Mn * En];
__device__ float g_a[Mn * 3];
__device__ float g_attn[Mn * 3];
__device__ float g_xproj[(size_t)Mn * Gn];
__device__ float g_enc[(size_t)Mn * Hn];
__device__ float g_ctx[(size_t)Mn * Hn];
__device__ float g_pred[Mn];
__device__ float g_h[2 * Bn * Hn];
__device__ unsigned g_bar_cnt;
__device__ unsigned g_bar_rel;

// ---- packed f32x2 helpers (Blackwell FFMA2; PTX-only) ----
__device__ __forceinline__ unsigned long long fma2(unsigned long long a,
                                                   unsigned long long b,
                                                   unsigned long long c) {
    unsigned long long d;
    asm("fma.rn.f32x2 %0, %1, %2, %3;" : "=l"(d) : "l"(a), "l"(b), "l"(c));
    return d;
}
__device__ __forceinline__ float2 unpack2(unsigned long long v) {
    float2 r; asm("mov.b64 {%0,%1}, %2;" : "=f"(r.x), "=f"(r.y) : "l"(v)); return r;
}
__device__ __forceinline__ unsigned long long pack2(float lo, float hi) {
    unsigned long long v; asm("mov.b64 %0, {%1,%2};" : "=l"(v) : "f"(lo), "f"(hi)); return v;
}

// ---- acquire/release grid barrier (no membar, no nanosleep) ----
__device__ __forceinline__ void grid_bar(unsigned phase) {
    __syncthreads();
    if (threadIdx.x == 0) {
        unsigned v;
        asm volatile("atom.acq_rel.gpu.add.u32 %0, [%1], %2;"
                     : "=r"(v) : "l"(&g_bar_cnt), "r"(1u) : "memory");
        if (v == phase * (unsigned)NBLK + (unsigned)(NBLK - 1)) {
            asm volatile("st.release.gpu.u32 [%0], %1;"
                         :: "l"(&g_bar_rel), "r"(phase + 1u) : "memory");
        } else {
            unsigned r;
            do {
                asm volatile("ld.acquire.gpu.u32 %0, [%1];"
                             : "=r"(r) : "l"(&g_bar_rel) : "memory");
            } while (r < phase + 1u);
        }
    }
    __syncthreads();
}

__device__ __forceinline__ float sigmoidf_(float x) { return 1.0f / (1.0f + expf(-x)); }

// ---------------------------------------------------------------------------
// SIMT SGEMM with packed f32x2 FMA: C[M,N] = act(A@B^T + bias1 + bias2)
// ---------------------------------------------------------------------------
__global__ void __launch_bounds__(256) sgemm_kernel(
    const float* __restrict__ A, const float* __restrict__ B, float* __restrict__ C,
    int M, int N, int K, int lda, int ldb, int koff,
    const float* __restrict__ bias1, const float* __restrict__ bias2, int relu)
{
    __shared__ float As[8][128];
    __shared__ float Bs[8][128];
    const int tid = threadIdx.x, bx = blockIdx.x, by = blockIdx.y;
    const int tx = tid & 15, ty = tid >> 4;
    const int arow = tid >> 1, acol = (tid & 1) * 4;
    const float* Ag = A + (size_t)(by * 128 + arow) * lda + acol;
    const float* Bg = B + (size_t)(bx * 128 + arow) * ldb + koff + acol;

    unsigned long long acc2[8][4];
    #pragma unroll
    for (int i = 0; i < 8; ++i)
        #pragma unroll
        for (int j = 0; j < 4; ++j) acc2[i][j] = 0ull;

    for (int k0 = 0; k0 < K; k0 += 8) {
        float4 av = *(const float4*)(Ag + k0);
        float b0 = Bg[k0], b1 = Bg[k0 + 1], b2 = Bg[k0 + 2], b3 = Bg[k0 + 3];
        As[acol + 0][arow] = av.x; As[acol + 1][arow] = av.y;
        As[acol + 2][arow] = av.z; As[acol + 3][arow] = av.w;
        Bs[acol + 0][arow] = b0;   Bs[acol + 1][arow] = b1;
        Bs[acol + 2][arow] = b2;   Bs[acol + 3][arow] = b3;
        __syncthreads();
        #pragma unroll
        for (int kk = 0; kk < 8; ++kk) {
            float4 ra0 = *(const float4*)&As[kk][ty * 8];
            float4 ra1 = *(const float4*)&As[kk][ty * 8 + 4];
            ulonglong2 rb0 = *(const ulonglong2*)&Bs[kk][tx * 8];
            ulonglong2 rb1 = *(const ulonglong2*)&Bs[kk][tx * 8 + 4];
            float ra[8] = {ra0.x, ra0.y, ra0.z, ra0.w, ra1.x, ra1.y, ra1.z, ra1.w};
            #pragma unroll
            for (int i = 0; i < 8; ++i) {
                unsigned long long ap = pack2(ra[i], ra[i]);
                acc2[i][0] = fma2(ap, rb0.x, acc2[i][0]);
                acc2[i][1] = fma2(ap, rb0.y, acc2[i][1]);
                acc2[i][2] = fma2(ap, rb1.x, acc2[i][2]);
                acc2[i][3] = fma2(ap, rb1.y, acc2[i][3]);
            }
        }
        __syncthreads();
    }
    #pragma unroll
    for (int i = 0; i < 8; ++i) {
        int m = by * 128 + ty * 8 + i;
        #pragma unroll
        for (int jp = 0; jp < 4; ++jp) {
            float2 v = unpack2(acc2[i][jp]);
            int n = bx * 128 + tx * 8 + jp * 2;
            float v0 = v.x, v1 = v.y;
            if (bias1) { v0 += bias1[n]; v1 += bias1[n + 1]; }
            if (bias2) { v0 += bias2[n]; v1 += bias2[n + 1]; }
            if (relu)  { v0 = fmaxf(v0, 0.f); v1 = fmaxf(v1, 0.f); }
            C[(size_t)m * N + n]     = v0;
            C[(size_t)m * N + n + 1] = v1;
        }
    }
}

__global__ void attn_logits_kernel(const float* __restrict__ a1,
                                   const float* __restrict__ W_a2,
                                   const float* __restrict__ b_a2,
                                   float* __restrict__ a)
{
    int gw = (blockIdx.x * blockDim.x + threadIdx.x) >> 5;
    int lane = threadIdx.x & 31;
    if (gw >= Mn) return;
    float4 v = ((const float4*)(a1 + (size_t)gw * En))[lane];
    #pragma unroll
    for (int l = 0; l < 3; ++l) {
        float4 wv = ((const float4*)(W_a2 + l * En))[lane];
        float s = v.x * wv.x + v.y * wv.y + v.z * wv.z + v.w * wv.w;
        #pragma unroll
        for (int o = 16; o; o >>= 1) s += __shfl_xor_sync(0xffffffffu, s, o);
        if (lane == 0) a[(size_t)gw * 3 + l] = s + b_a2[l];
    }
}

__global__ void softmax_time_kernel(const float* __restrict__ a, float* __restrict__ attn)
{
    __shared__ float red[256];
    int b = blockIdx.x / 3, l = blockIdx.x - b * 3;
    const float* base = a + (size_t)b * Sn * 3 + l;
    float mx = -3.4e38f;
    for (int s = threadIdx.x; s < Sn; s += 256) mx = fmaxf(mx, base[(size_t)s * 3]);
    red[threadIdx.x] = mx; __syncthreads();
    for (int o = 128; o; o >>= 1) {
        if (threadIdx.x < o) red[threadIdx.x] = fmaxf(red[threadIdx.x], red[threadIdx.x + o]);
        __syncthreads();
    }
    mx = red[0]; __syncthreads();
    float sum = 0.f;
    for (int s = threadIdx.x; s < Sn; s += 256) sum += expf(base[(size_t)s * 3] - mx);
    red[threadIdx.x] = sum; __syncthreads();
    for (int o = 128; o; o >>= 1) {
        if (threadIdx.x < o) red[threadIdx.x] += red[threadIdx.x + o];
        __syncthreads();
    }
    float inv = 1.f / red[0];
    float* ob = attn + (size_t)b * Sn * 3 + l;
    for (int s = threadIdx.x; s < Sn; s += 256)
        ob[(size_t)s * 3] = expf(base[(size_t)s * 3] - mx) * inv;
}

__global__ void context_kernel(const float* __restrict__ attn,
                               const float* __restrict__ enc,
                               float* __restrict__ ctx)
{
    int m = blockIdx.x;
    int t = m & (Sn - 1);
    float a0 = attn[(size_t)m * 3 + 0];
    float a1 = attn[(size_t)m * 3 + 1];
    float a2 = attn[(size_t)m * 3 + 2];
    float4 e0 = ((const float4*)(enc + (size_t)m * Hn))[threadIdx.x];
    float4 r; r.x = a0 * e0.x; r.y = a0 * e0.y; r.z = a0 * e0.z; r.w = a0 * e0.w;
    if (t >= 1) {
        float4 e1 = ((const float4*)(enc + (size_t)(m - 1) * Hn))[threadIdx.x];
        r.x += a1 * e1.x; r.y += a1 * e1.y; r.z += a1 * e1.z; r.w += a1 * e1.w;
    }
    if (t >= 2) {
        float4 e2 = ((const float4*)(enc + (size_t)(m - 2) * Hn))[threadIdx.x];
        r.x += a2 * e2.x; r.y += a2 * e2.y; r.z += a2 * e2.z; r.w += a2 * e2.w;
    }
    ((float4*)(ctx + (size_t)m * Hn))[threadIdx.x] = r;
}

__global__ void init_enc_kernel(const float* __restrict__ h0)
{
    int i = blockIdx.x * 256 + threadIdx.x;
    if (i < Bn * Hn) g_h[i] = h0[i & (Hn - 1)];
    if (i == 0) { g_bar_cnt = 0u; g_bar_rel = 0u; }
}

__global__ void init_dec_kernel(const float* __restrict__ h0, const float* __restrict__ b_o2)
{
    int i = blockIdx.x * 256 + threadIdx.x;
    if (i < Bn * Hn) g_h[i] = h0[i & (Hn - 1)];
    if (i < Mn) g_pred[i] = b_o2[0];
    if (i == 0) { g_bar_cnt = 0u; g_bar_rel = 0u; }
}

#define ENC_SMEM ((16 * 512 + 32 * 516 + 128 * 4) * 4)
__global__ void __launch_bounds__(256, 1) lstm_enc_kernel(
    const float* __restrict__ xproj, const float* __restrict__ Whh,
    const float* __restrict__ c0, const int* __restrict__ lengths,
    float* __restrict__ enc_out)
{
    extern __shared__ float sm[];
    float* w_s   = sm;
    float* h_s   = sm + 16 * 512;
    float* red_s = h_s + 32 * 516;

    const int bl = blockIdx.x, tid = threadIdx.x;
    const int half = tid >> 7, tl = tid & 127;
    const int b = tl & 31, jj = tl >> 5;
    const int j = bl * 4 + jj;

    for (int i = tid; i < 16 * 512; i += 256) {
        int lr = i >> 9, k = i & 511;
        int g = lr >> 2, j2 = lr & 3;
        w_s[i] = Whh[(size_t)(g * Hn + bl * 4 + j2) * Hn + k];
    }
    float c_reg = (half == 0) ? c0[j] : 0.f;
    const int len_b = lengths[b];
    __syncthreads();

    const ulonglong2* w0 = (const ulonglong2*)(w_s + (0 * 4 + jj) * 512);
    const ulonglong2* w1 = (const ulonglong2*)(w_s + (1 * 4 + jj) * 512);
    const ulonglong2* w2 = (const ulonglong2*)(w_s + (2 * 4 + jj) * 512);
    const ulonglong2* w3 = (const ulonglong2*)(w_s + (3 * 4 + jj) * 512);
    const ulonglong2* hv = (const ulonglong2*)(h_s + b * 516);
    const int kbeg = half * 64, kend = kbeg + 64;

    for (int t = 0; t < Sn; ++t) {
        const float4* src = (const float4*)(g_h + (t & 1) * (Bn * Hn));
        #pragma unroll
        for (int i = 0; i < 16; ++i) {
            int idx = tid + i * 256;
            float4 v = __ldcg(src + idx);
            ((float4*)(h_s + (idx >> 7) * 516))[idx & 127] = v;
        }
        __syncthreads();

        unsigned long long s0a = 0ull, s0b = 0ull, s1a = 0ull, s1b = 0ull;
        unsigned long long s2a = 0ull, s2b = 0ull, s3a = 0ull, s3b = 0ull;
        #pragma unroll 8
        for (int kk = kbeg; kk < kend; ++kk) {
            ulonglong2 h2 = hv[kk]; ulonglong2 w;
            w = w0[kk]; s0a = fma2(h2.x, w.x, s0a); s0b = fma2(h2.y, w.y, s0b);
            w = w1[kk]; s1a = fma2(h2.x, w.x, s1a); s1b = fma2(h2.y, w.y, s1b);
            w = w2[kk]; s2a = fma2(h2.x, w.x, s2a); s2b = fma2(h2.y, w.y, s2b);
            w = w3[kk]; s3a = fma2(h2.x, w.x, s3a); s3b = fma2(h2.y, w.y, s3b);
        }
        float2 u0 = unpack2(s0a), v0 = unpack2(s0b);
        float2 u1 = unpack2(s1a), v1 = unpack2(s1b);
        float2 u2 = unpack2(s2a), v2 = unpack2(s2b);
        float2 u3 = unpack2(s3a), v3 = unpack2(s3b);
        float a0 = (u0.x + u0.y) + (v0.x + v0.y);
        float a1 = (u1.x + u1.y) + (v1.x + v1.y);
        float a2 = (u2.x + u2.y) + (v2.x + v2.y);
        float a3 = (u3.x + u3.y) + (v3.x + v3.y);

        if (half == 1) {
            float* r = red_s + tl * 4;
            r[0] = a0; r[1] = a1; r[2] = a2; r[3] = a3;
        }
        __syncthreads();
        if (half == 0) {
            const float* r  = red_s + tl * 4;
            const float* xp = xproj + (size_t)(b * Sn + t) * Gn + j;
            float gi = a0 + r[0] + xp[0 * Hn];
            float gf = a1 + r[1] + xp[1 * Hn];
            float gg = a2 + r[2] + xp[2 * Hn];
            float go = a3 + r[3] + xp[3 * Hn];
            float si = sigmoidf_(gi), sf = sigmoidf_(gf), so = sigmoidf_(go);
            c_reg = sf * c_reg + si * tanhf(gg);
            float hh = so * tanhf(c_reg);
            __stcg(&g_h[((t + 1) & 1) * (Bn * Hn) + b * Hn + j], hh);
            enc_out[(size_t)(b * Sn + t) * Hn + j] = (t < len_b) ? hh : 0.f;
        }
        grid_bar((unsigned)t);
    }
}

#define DEC_SMEM ((16 * 512 + 32 * 516 + 128 * 4 + 512 + 16) * 4)
__global__ void __launch_bounds__(256, 1) lstm_dec_kernel(
    const float* __restrict__ ctxproj, const float* __restrict__ Whh,
    const float* __restrict__ Wih, const float* __restrict__ c0,
    const float* __restrict__ W_o1, const float* __restrict__ b_o1,
    const float* __restrict__ W_o2)
{
    extern __shared__ float sm[];
    float* w_s   = sm;
    float* h_s   = sm + 16 * 512;
    float* red_s = h_s + 32 * 516;
    float* wo1_s = red_s + 512;
    float* wp_s  = wo1_s + 512;

    const int bl = blockIdx.x, tid = threadIdx.x;
    const int half = tid >> 7, tl = tid & 127;
    const int b = tl & 31, jj = tl >> 5;
    const int j = bl * 4 + jj;

    for (int i = tid; i < 16 * 512; i += 256) {
        int lr = i >> 9, k = i & 511;
        int g = lr >> 2, j2 = lr & 3;
        w_s[i] = Whh[(size_t)(g * Hn + bl * 4 + j2) * Hn + k];
    }
    for (int i = tid; i < 512; i += 256) wo1_s[i] = W_o1[(size_t)bl * Hn + i];
    if (tid < 16) {
        int g = tid >> 2, j2 = tid & 3;
        wp_s[tid] = Wih[(size_t)(g * Hn + bl * 4 + j2) * 513];
    }
    const float wo2 = W_o2[bl];
    const float bo1 = b_o1[bl];
    float c_reg = (half == 0) ? c0[j] : 0.f;
    __syncthreads();

    const ulonglong2* w0 = (const ulonglong2*)(w_s + (0 * 4 + jj) * 512);
    const ulonglong2* w1 = (const ulonglong2*)(w_s + (1 * 4 + jj) * 512);
    const ulonglong2* w2 = (const ulonglong2*)(w_s + (2 * 4 + jj) * 512);
    const ulonglong2* w3 = (const ulonglong2*)(w_s + (3 * 4 + jj) * 512);
    const ulonglong2* hv = (const ulonglong2*)(h_s + b * 516);
    const int kbeg = half * 64, kend = kbeg + 64;
    const int warp = tid >> 5, lane = tid & 31;

    for (int t = 0; t < Sn; ++t) {
        const float4* src = (const float4*)(g_h + (t & 1) * (Bn * Hn));
        #pragma unroll
        for (int i = 0; i < 16; ++i) {
            int idx = tid + i * 256;
            float4 v = __ldcg(src + idx);
            ((float4*)(h_s + (idx >> 7) * 516))[idx & 127] = v;
        }
        __syncthreads();

        // output MLP partials for step t-1 (atomics overlap with dots below)
        if (t > 0) {
            #pragma unroll
            for (int bi = 0; bi < 4; ++bi) {
                int bb = warp * 4 + bi;
                float s = 0.f;
                #pragma unroll
                for (int kk = 0; kk < 16; ++kk) {
                    int k = kk * 32 + lane;
                    s += wo1_s[k] * h_s[bb * 516 + k];
                }
                #pragma unroll
                for (int o = 16; o; o >>= 1) s += __shfl_xor_sync(0xffffffffu, s, o);
                if (lane == 0) {
                    float o1 = fmaxf(s + bo1, 0.f);
                    atomicAdd(&g_pred[bb * Sn + (t - 1)], o1 * wo2);
                }
            }
        }

        unsigned long long s0a = 0ull, s0b = 0ull, s1a = 0ull, s1b = 0ull;
        unsigned long long s2a = 0ull, s2b = 0ull, s3a = 0ull, s3b = 0ull;
        #pragma unroll 8
        for (int kk = kbeg; kk < kend; ++kk) {
            ulonglong2 h2 = hv[kk]; ulonglong2 w;
            w = w0[kk]; s0a = fma2(h2.x, w.x, s0a); s0b = fma2(h2.y, w.y, s0b);
            w = w1[kk]; s1a = fma2(h2.x, w.x, s1a); s1b = fma2(h2.y, w.y, s1b);
            w = w2[kk]; s2a = fma2(h2.x, w.x, s2a); s2b = fma2(h2.y, w.y, s2b);
            w = w3[kk]; s3a = fma2(h2.x, w.x, s3a); s3b = fma2(h2.y, w.y, s3b);
        }
        float2 u0 = unpack2(s0a), vv0 = unpack2(s0b);
        float2 u1 = unpack2(s1a), vv1 = unpack2(s1b);
        float2 u2 = unpack2(s2a), vv2 = unpack2(s2b);
        float2 u3 = unpack2(s3a), vv3 = unpack2(s3b);
        float a0 = (u0.x + u0.y) + (vv0.x + vv0.y);
        float a1 = (u1.x + u1.y) + (vv1.x + vv1.y);
        float a2 = (u2.x + u2.y) + (vv2.x + vv2.y);
        float a3 = (u3.x + u3.y) + (vv3.x + vv3.y);

        if (half == 1) {
            float* r = red_s + tl * 4;
            r[0] = a0; r[1] = a1; r[2] = a2; r[3] = a3;
        }
        grid_bar(2u * (unsigned)t);   // p[t-1] now complete; red_s also synced

        if (half == 0) {
            float p_prev = (t > 0) ? __ldcg(&g_pred[b * Sn + (t - 1)]) : 0.f;
            const float* r  = red_s + tl * 4;
            const float* xp = ctxproj + (size_t)(b * Sn + t) * Gn + j;
            float gi = a0 + r[0] + xp[0 * Hn] + p_prev * wp_s[0 * 4 + jj];
            float gf = a1 + r[1] + xp[1 * Hn] + p_prev * wp_s[1 * 4 + jj];
            float gg = a2 + r[2] + xp[2 * Hn] + p_prev * wp_s[2 * 4 + jj];
            float go = a3 + r[3] + xp[3 * Hn] + p_prev * wp_s[3 * 4 + jj];
            float si = sigmoidf_(gi), sf = sigmoidf_(gf), so = sigmoidf_(go);
            c_reg = sf * c_reg + si * tanhf(gg);
            float hh = so * tanhf(c_reg);
            __stcg(&g_h[((t + 1) & 1) * (Bn * Hn) + b * Hn + j], hh);
        }
        grid_bar(2u * (unsigned)t + 1u);
    }

    {
        const float4* src = (const float4*)(g_h + (Sn & 1) * (Bn * Hn));
        #pragma unroll
        for (int i = 0; i < 16; ++i) {
            int idx = tid + i * 256;
            float4 v = __ldcg(src + idx);
            ((float4*)(h_s + (idx >> 7) * 516))[idx & 127] = v;
        }
        __syncthreads();
        #pragma unroll
        for (int bi = 0; bi < 4; ++bi) {
            int bb = warp * 4 + bi;
            float s = 0.f;
            #pragma unroll
            for (int kk = 0; kk < 16; ++kk) {
                int k = kk * 32 + lane;
                s += wo1_s[k] * h_s[bb * 516 + k];
            }
            #pragma unroll
            for (int o = 16; o; o >>= 1) s += __shfl_xor_sync(0xffffffffu, s, o);
            if (lane == 0) {
                float o1 = fmaxf(s + bo1, 0.f);
                atomicAdd(&g_pred[bb * Sn + (Sn - 1)], o1 * wo2);
            }
        }
    }
}

__global__ void finalize_kernel(const float* __restrict__ mask, float* __restrict__ out)
{
    int i = blockIdx.x * 256 + threadIdx.x;
    if (i < Mn) out[i] = g_pred[i] * mask[i];
}

extern "C" void kernel_launch(void* const* d_in, const int* in_sizes, int n_in,
                              void* d_out, int out_size)
{
    const float* inputs  = (const float*)d_in[0];
    const float* mask    = (const float*)d_in[1];
    const int*   lengths = (const int*)  d_in[2];
    const float* W_e     = (const float*)d_in[3];
    const float* b_e     = (const float*)d_in[4];
    const float* W_a1    = (const float*)d_in[5];
    const float* b_a1    = (const float*)d_in[6];
    const float* W_a2    = (const float*)d_in[7];
    const float* b_a2    = (const float*)d_in[8];
    const float* Wih_e   = (const float*)d_in[9];
    const float* Whh_e   = (const float*)d_in[10];
    const float* bih_e   = (const float*)d_in[11];
    const float* bhh_e   = (const float*)d_in[12];
    const float* enc_h0  = (const float*)d_in[13];
    const float* enc_c0  = (const float*)d_in[14];
    const float* Wih_d   = (const float*)d_in[15];
    const float* Whh_d   = (const float*)d_in[16];
    const float* bih_d   = (const float*)d_in[17];
    const float* bhh_d   = (const float*)d_in[18];
    const float* dec_h0  = (const float*)d_in[19];
    const float* dec_c0  = (const float*)d_in[20];
    const float* W_o1    = (const float*)d_in[21];
    const float* b_o1    = (const float*)d_in[22];
    const float* W_o2    = (const float*)d_in[23];
    const float* b_o2    = (const float*)d_in[24];
    float* out = (float*)d_out;

    float *p_embed, *p_a1, *p_a, *p_attn, *p_xproj, *p_enc, *p_ctx;
    cudaGetSymbolAddress((void**)&p_embed, g_embed);
    cudaGetSymbolAddress((void**)&p_a1,    g_a1);
    cudaGetSymbolAddress((void**)&p_a,     g_a);
    cudaGetSymbolAddress((void**)&p_attn,  g_attn);
    cudaGetSymbolAddress((void**)&p_xproj, g_xproj);
    cudaGetSymbolAddress((void**)&p_enc,   g_enc);
    cudaGetSymbolAddress((void**)&p_ctx,   g_ctx);

    cudaFuncSetAttribute(lstm_enc_kernel, cudaFuncAttributeMaxDynamicSharedMemorySize, ENC_SMEM);
    cudaFuncSetAttribute(lstm_dec_kernel, cudaFuncAttributeMaxDynamicSharedMemorySize, DEC_SMEM);

    sgemm_kernel<<<dim3(En / 128, Mn / 128), 256>>>(
        inputs, W_e, p_embed, Mn, En, 1024, 1024, 1024, 0, b_e, nullptr, 1);
    sgemm_kernel<<<dim3(En / 128, Mn / 128), 256>>>(
        p_embed, W_a1, p_a1, Mn, En, En, En, En, 0, b_a1, nullptr, 1);
    attn_logits_kernel<<<Mn / 8, 256>>>(p_a1, W_a2, b_a2, p_a);
    softmax_time_kernel<<<Bn * 3, 256>>>(p_a, p_attn);
    sgemm_kernel<<<dim3(Gn / 128, Mn / 128), 256>>>(
        p_embed, Wih_e, p_xproj, Mn, Gn, En, En, En, 0, bih_e, bhh_e, 0);
    init_enc_kernel<<<(Bn * Hn + 255) / 256, 256>>>(enc_h0);
    lstm_enc_kernel<<<NBLK, 256, ENC_SMEM>>>(p_xproj, Whh_e, enc_c0, lengths, p_enc);
    context_kernel<<<Mn, Hn / 4>>>(p_attn, p_enc, p_ctx);
    sgemm_kernel<<<dim3(Gn / 128, Mn / 128), 256>>>(
        p_ctx, Wih_d, p_xproj, Mn, Gn, Hn, Hn, Hn + 1, 1, bih_d, bhh_d, 0);
    init_dec_kernel<<<(Mn + 255) / 256, 256>>>(dec_h0, b_o2);
    lstm_dec_kernel<<<NBLK, 256, DEC_SMEM>>>(p_xproj, Whh_d, Wih_d, dec_c0, W_o1, b_o1, W_o2);
    finalize_kernel<<<(Mn + 255) / 256, 256>>>(mask, out);
}

// round 6
// speedup vs baseline: 1.1390x; 1.0111x over previous
#include <cuda_runtime.h>
#include <math.h>

#define Bn   32
#define Sn   1024
#define En   128
#define Hn   512
#define Gn   2048
#define Mn   32768
#define NBG  4      // batch groups (8 batches each)
#define NJG  32     // j groups (16 hidden units each)
#define GRP  32     // blocks per batch group

__device__ float g_embed[Mn * En];
__device__ float g_a1[Mn * En];
__device__ float g_a[Mn * 3];
__device__ float g_attn[Mn * 3];
__device__ float g_xproj[(size_t)Mn * Gn];
__device__ float g_enc[(size_t)Mn * Hn];
__device__ float g_ctx[(size_t)Mn * Hn];
__device__ float g_pred[Mn];
__device__ float g_h[2 * Bn * Hn];
__device__ unsigned g_cnt[NBG * 32];
__device__ unsigned g_rel[NBG * 32];

// ---- packed f32x2 helpers ----
__device__ __forceinline__ unsigned long long fma2(unsigned long long a,
                                                   unsigned long long b,
                                                   unsigned long long c) {
    unsigned long long d;
    asm("fma.rn.f32x2 %0, %1, %2, %3;" : "=l"(d) : "l"(a), "l"(b), "l"(c));
    return d;
}
__device__ __forceinline__ float2 unpack2(unsigned long long v) {
    float2 r; asm("mov.b64 {%0,%1}, %2;" : "=f"(r.x), "=f"(r.y) : "l"(v)); return r;
}
__device__ __forceinline__ unsigned long long pack2(float lo, float hi) {
    unsigned long long v; asm("mov.b64 %0, {%1,%2};" : "=l"(v) : "f"(lo), "f"(hi)); return v;
}

// ---- per-group acquire/release barrier (GRP arrivals) ----
__device__ __forceinline__ void grp_bar(int g, unsigned phase) {
    __syncthreads();
    if (threadIdx.x == 0) {
        unsigned v;
        asm volatile("atom.acq_rel.gpu.add.u32 %0, [%1], %2;"
                     : "=r"(v) : "l"(&g_cnt[g * 32]), "r"(1u) : "memory");
        if (v == phase * (unsigned)GRP + (unsigned)(GRP - 1)) {
            asm volatile("st.release.gpu.u32 [%0], %1;"
                         :: "l"(&g_rel[g * 32]), "r"(phase + 1u) : "memory");
        } else {
            unsigned r;
            do {
                asm volatile("ld.acquire.gpu.u32 %0, [%1];"
                             : "=r"(r) : "l"(&g_rel[g * 32]) : "memory");
            } while (r < phase + 1u);
        }
    }
    __syncthreads();
}

__device__ __forceinline__ float sigmoidf_(float x) { return 1.0f / (1.0f + expf(-x)); }

// ---------------------------------------------------------------------------
// SIMT SGEMM with packed f32x2 FMA (unchanged from R5)
// ---------------------------------------------------------------------------
__global__ void __launch_bounds__(256) sgemm_kernel(
    const float* __restrict__ A, const float* __restrict__ B, float* __restrict__ C,
    int M, int N, int K, int lda, int ldb, int koff,
    const float* __restrict__ bias1, const float* __restrict__ bias2, int relu)
{
    __shared__ float As[8][128];
    __shared__ float Bs[8][128];
    const int tid = threadIdx.x, bx = blockIdx.x, by = blockIdx.y;
    const int tx = tid & 15, ty = tid >> 4;
    const int arow = tid >> 1, acol = (tid & 1) * 4;
    const float* Ag = A + (size_t)(by * 128 + arow) * lda + acol;
    const float* Bg = B + (size_t)(bx * 128 + arow) * ldb + koff + acol;

    unsigned long long acc2[8][4];
    #pragma unroll
    for (int i = 0; i < 8; ++i)
        #pragma unroll
        for (int j = 0; j < 4; ++j) acc2[i][j] = 0ull;

    for (int k0 = 0; k0 < K; k0 += 8) {
        float4 av = *(const float4*)(Ag + k0);
        float b0 = Bg[k0], b1 = Bg[k0 + 1], b2 = Bg[k0 + 2], b3 = Bg[k0 + 3];
        As[acol + 0][arow] = av.x; As[acol + 1][arow] = av.y;
        As[acol + 2][arow] = av.z; As[acol + 3][arow] = av.w;
        Bs[acol + 0][arow] = b0;   Bs[acol + 1][arow] = b1;
        Bs[acol + 2][arow] = b2;   Bs[acol + 3][arow] = b3;
        __syncthreads();
        #pragma unroll
        for (int kk = 0; kk < 8; ++kk) {
            float4 ra0 = *(const float4*)&As[kk][ty * 8];
            float4 ra1 = *(const float4*)&As[kk][ty * 8 + 4];
            ulonglong2 rb0 = *(const ulonglong2*)&Bs[kk][tx * 8];
            ulonglong2 rb1 = *(const ulonglong2*)&Bs[kk][tx * 8 + 4];
            float ra[8] = {ra0.x, ra0.y, ra0.z, ra0.w, ra1.x, ra1.y, ra1.z, ra1.w};
            #pragma unroll
            for (int i = 0; i < 8; ++i) {
                unsigned long long ap = pack2(ra[i], ra[i]);
                acc2[i][0] = fma2(ap, rb0.x, acc2[i][0]);
                acc2[i][1] = fma2(ap, rb0.y, acc2[i][1]);
                acc2[i][2] = fma2(ap, rb1.x, acc2[i][2]);
                acc2[i][3] = fma2(ap, rb1.y, acc2[i][3]);
            }
        }
        __syncthreads();
    }
    #pragma unroll
    for (int i = 0; i < 8; ++i) {
        int m = by * 128 + ty * 8 + i;
        #pragma unroll
        for (int jp = 0; jp < 4; ++jp) {
            float2 v = unpack2(acc2[i][jp]);
            int n = bx * 128 + tx * 8 + jp * 2;
            float v0 = v.x, v1 = v.y;
            if (bias1) { v0 += bias1[n]; v1 += bias1[n + 1]; }
            if (bias2) { v0 += bias2[n]; v1 += bias2[n + 1]; }
            if (relu)  { v0 = fmaxf(v0, 0.f); v1 = fmaxf(v1, 0.f); }
            C[(size_t)m * N + n]     = v0;
            C[(size_t)m * N + n + 1] = v1;
        }
    }
}

__global__ void attn_logits_kernel(const float* __restrict__ a1,
                                   const float* __restrict__ W_a2,
                                   const float* __restrict__ b_a2,
                                   float* __restrict__ a)
{
    int gw = (blockIdx.x * blockDim.x + threadIdx.x) >> 5;
    int lane = threadIdx.x & 31;
    if (gw >= Mn) return;
    float4 v = ((const float4*)(a1 + (size_t)gw * En))[lane];
    #pragma unroll
    for (int l = 0; l < 3; ++l) {
        float4 wv = ((const float4*)(W_a2 + l * En))[lane];
        float s = v.x * wv.x + v.y * wv.y + v.z * wv.z + v.w * wv.w;
        #pragma unroll
        for (int o = 16; o; o >>= 1) s += __shfl_xor_sync(0xffffffffu, s, o);
        if (lane == 0) a[(size_t)gw * 3 + l] = s + b_a2[l];
    }
}

__global__ void softmax_time_kernel(const float* __restrict__ a, float* __restrict__ attn)
{
    __shared__ float red[256];
    int b = blockIdx.x / 3, l = blockIdx.x - b * 3;
    const float* base = a + (size_t)b * Sn * 3 + l;
    float mx = -3.4e38f;
    for (int s = threadIdx.x; s < Sn; s += 256) mx = fmaxf(mx, base[(size_t)s * 3]);
    red[threadIdx.x] = mx; __syncthreads();
    for (int o = 128; o; o >>= 1) {
        if (threadIdx.x < o) red[threadIdx.x] = fmaxf(red[threadIdx.x], red[threadIdx.x + o]);
        __syncthreads();
    }
    mx = red[0]; __syncthreads();
    float sum = 0.f;
    for (int s = threadIdx.x; s < Sn; s += 256) sum += expf(base[(size_t)s * 3] - mx);
    red[threadIdx.x] = sum; __syncthreads();
    for (int o = 128; o; o >>= 1) {
        if (threadIdx.x < o) red[threadIdx.x] += red[threadIdx.x + o];
        __syncthreads();
    }
    float inv = 1.f / red[0];
    float* ob = attn + (size_t)b * Sn * 3 + l;
    for (int s = threadIdx.x; s < Sn; s += 256)
        ob[(size_t)s * 3] = expf(base[(size_t)s * 3] - mx) * inv;
}

__global__ void context_kernel(const float* __restrict__ attn,
                               const float* __restrict__ enc,
                               float* __restrict__ ctx)
{
    int m = blockIdx.x;
    int t = m & (Sn - 1);
    float a0 = attn[(size_t)m * 3 + 0];
    float a1 = attn[(size_t)m * 3 + 1];
    float a2 = attn[(size_t)m * 3 + 2];
    float4 e0 = ((const float4*)(enc + (size_t)m * Hn))[threadIdx.x];
    float4 r; r.x = a0 * e0.x; r.y = a0 * e0.y; r.z = a0 * e0.z; r.w = a0 * e0.w;
    if (t >= 1) {
        float4 e1 = ((const float4*)(enc + (size_t)(m - 1) * Hn))[threadIdx.x];
        r.x += a1 * e1.x; r.y += a1 * e1.y; r.z += a1 * e1.z; r.w += a1 * e1.w;
    }
    if (t >= 2) {
        float4 e2 = ((const float4*)(enc + (size_t)(m - 2) * Hn))[threadIdx.x];
        r.x += a2 * e2.x; r.y += a2 * e2.y; r.z += a2 * e2.z; r.w += a2 * e2.w;
    }
    ((float4*)(ctx + (size_t)m * Hn))[threadIdx.x] = r;
}

__global__ void init_enc_kernel(const float* __restrict__ h0)
{
    int i = blockIdx.x * 256 + threadIdx.x;
    if (i < Bn * Hn) g_h[i] = h0[i & (Hn - 1)];
    if (i < NBG * 32) { g_cnt[i] = 0u; g_rel[i] = 0u; }
}

__global__ void init_dec_kernel(const float* __restrict__ h0, const float* __restrict__ b_o2)
{
    int i = blockIdx.x * 256 + threadIdx.x;
    if (i < Bn * Hn) g_h[i] = h0[i & (Hn - 1)];
    if (i < Mn) g_pred[i] = b_o2[0];
    if (i < NBG * 32) { g_cnt[i] = 0u; g_rel[i] = 0u; }
}

// ===========================================================================
// Encoder LSTM: 128 blocks = 4 batch-groups x 32 j-groups.
// Block (bg,jg): 16 hidden units (64 gate rows, 132KB smem weights), 8 batches.
// smem: w[64][516], h[8][516], red[512]
// ===========================================================================
#define ENC_SMEM ((64 * 516 + 8 * 516 + 512) * 4)
__global__ void __launch_bounds__(256, 1) lstm_enc_kernel(
    const float* __restrict__ xproj, const float* __restrict__ Whh,
    const float* __restrict__ c0, const int* __restrict__ lengths,
    float* __restrict__ enc_out)
{
    extern __shared__ float sm[];
    float* w_s   = sm;                 // [64][516]
    float* h_s   = sm + 64 * 516;      // [8][516]
    float* red_s = h_s + 8 * 516;      // [128][4]

    const int bg = blockIdx.x & 3, jg = blockIdx.x >> 2;
    const int tid = threadIdx.x;
    const int half = tid >> 7, tl = tid & 127;
    const int jx = tl & 15, bl = tl >> 4;
    const int j = jg * 16 + jx;
    const int b = bg * 8 + bl;

    for (int i = tid; i < 64 * 512; i += 256) {
        int lr = i >> 9, k = i & 511;            // lr = g*16 + jx2
        w_s[lr * 516 + k] = Whh[(size_t)((lr >> 4) * Hn + jg * 16 + (lr & 15)) * Hn + k];
    }
    float c_reg = (half == 0) ? c0[j] : 0.f;
    const int len_b = lengths[b];
    __syncthreads();

    const ulonglong2* w0 = (const ulonglong2*)(w_s + (0 * 16 + jx) * 516 + half * 256);
    const ulonglong2* w1 = (const ulonglong2*)(w_s + (1 * 16 + jx) * 516 + half * 256);
    const ulonglong2* w2 = (const ulonglong2*)(w_s + (2 * 16 + jx) * 516 + half * 256);
    const ulonglong2* w3 = (const ulonglong2*)(w_s + (3 * 16 + jx) * 516 + half * 256);
    const ulonglong2* hv = (const ulonglong2*)(h_s + bl * 516 + half * 256);

    for (int t = 0; t < Sn; ++t) {
        // stage h for 8 batches (16KB) + prefetch gate inputs
        const float4* src = (const float4*)(g_h + (t & 1) * (Bn * Hn) + bg * 8 * Hn);
        #pragma unroll
        for (int i = 0; i < 4; ++i) {
            int idx = tid + i * 256;
            float4 v = __ldcg(src + idx);
            ((float4*)(h_s + (idx >> 7) * 516))[idx & 127] = v;
        }
        float xp0 = 0.f, xp1 = 0.f, xp2 = 0.f, xp3 = 0.f;
        if (half == 0) {
            const float* xp = xproj + ((size_t)b * Sn + t) * Gn + j;
            xp0 = xp[0]; xp1 = xp[512]; xp2 = xp[1024]; xp3 = xp[1536];
        }
        __syncthreads();

        unsigned long long s0 = 0ull, s1 = 0ull, s2 = 0ull, s3 = 0ull;
        #pragma unroll 8
        for (int kk = 0; kk < 64; ++kk) {
            ulonglong2 h2 = hv[kk]; ulonglong2 w;
            w = w0[kk]; s0 = fma2(h2.x, w.x, s0); s0 = fma2(h2.y, w.y, s0);
            w = w1[kk]; s1 = fma2(h2.x, w.x, s1); s1 = fma2(h2.y, w.y, s1);
            w = w2[kk]; s2 = fma2(h2.x, w.x, s2); s2 = fma2(h2.y, w.y, s2);
            w = w3[kk]; s3 = fma2(h2.x, w.x, s3); s3 = fma2(h2.y, w.y, s3);
        }
        float2 u0 = unpack2(s0), u1 = unpack2(s1), u2 = unpack2(s2), u3 = unpack2(s3);
        float a0 = u0.x + u0.y, a1 = u1.x + u1.y, a2 = u2.x + u2.y, a3 = u3.x + u3.y;

        if (half == 1) {
            float* r = red_s + tl * 4;
            r[0] = a0; r[1] = a1; r[2] = a2; r[3] = a3;
        }
        __syncthreads();
        if (half == 0) {
            const float* r = red_s + tl * 4;
            float gi = a0 + r[0] + xp0;
            float gf = a1 + r[1] + xp1;
            float gg = a2 + r[2] + xp2;
            float go = a3 + r[3] + xp3;
            float si = sigmoidf_(gi), sf = sigmoidf_(gf), so = sigmoidf_(go);
            c_reg = sf * c_reg + si * tanhf(gg);
            float hh = so * tanhf(c_reg);
            __stcg(&g_h[((t + 1) & 1) * (Bn * Hn) + b * Hn + j], hh);
            enc_out[((size_t)b * Sn + t) * Hn + j] = (t < len_b) ? hh : 0.f;
        }
        grp_bar(bg, (unsigned)t);
    }
}

// ===========================================================================
// Decoder LSTM: same topology + scalar feedback p + output MLP.
// Block (bg,jg) also owns E-rows jg*4..jg*4+3 of W_o1/W_o2.
// smem: + wo1[4][516], wp[64]
// ===========================================================================
#define DEC_SMEM ((64 * 516 + 8 * 516 + 512 + 4 * 516 + 64) * 4)
__global__ void __launch_bounds__(256, 1) lstm_dec_kernel(
    const float* __restrict__ ctxproj, const float* __restrict__ Whh,
    const float* __restrict__ Wih, const float* __restrict__ c0,
    const float* __restrict__ W_o1, const float* __restrict__ b_o1,
    const float* __restrict__ W_o2)
{
    extern __shared__ float sm[];
    float* w_s   = sm;                 // [64][516]
    float* h_s   = sm + 64 * 516;      // [8][516]
    float* red_s = h_s + 8 * 516;      // [128][4]
    float* wo1_s = red_s + 512;        // [4][516]
    float* wp_s  = wo1_s + 4 * 516;    // [64]

    const int bg = blockIdx.x & 3, jg = blockIdx.x >> 2;
    const int tid = threadIdx.x;
    const int half = tid >> 7, tl = tid & 127;
    const int jx = tl & 15, bl = tl >> 4;
    const int j = jg * 16 + jx;
    const int b = bg * 8 + bl;
    const int warp = tid >> 5, lane = tid & 31;

    for (int i = tid; i < 64 * 512; i += 256) {
        int lr = i >> 9, k = i & 511;
        w_s[lr * 516 + k] = Whh[(size_t)((lr >> 4) * Hn + jg * 16 + (lr & 15)) * Hn + k];
    }
    for (int i = tid; i < 4 * 512; i += 256) {
        int e = i >> 9, k = i & 511;
        wo1_s[e * 516 + k] = W_o1[(size_t)(jg * 4 + e) * Hn + k];
    }
    if (tid < 64) {
        wp_s[tid] = Wih[(size_t)((tid >> 4) * Hn + jg * 16 + (tid & 15)) * 513];
    }
    float wo2_r[4], bo1_r[4];
    #pragma unroll
    for (int e = 0; e < 4; ++e) { wo2_r[e] = W_o2[jg * 4 + e]; bo1_r[e] = b_o1[jg * 4 + e]; }
    float c_reg = (half == 0) ? c0[j] : 0.f;
    __syncthreads();

    const ulonglong2* w0 = (const ulonglong2*)(w_s + (0 * 16 + jx) * 516 + half * 256);
    const ulonglong2* w1 = (const ulonglong2*)(w_s + (1 * 16 + jx) * 516 + half * 256);
    const ulonglong2* w2 = (const ulonglong2*)(w_s + (2 * 16 + jx) * 516 + half * 256);
    const ulonglong2* w3 = (const ulonglong2*)(w_s + (3 * 16 + jx) * 516 + half * 256);
    const ulonglong2* hv = (const ulonglong2*)(h_s + bl * 516 + half * 256);

    for (int t = 0; t < Sn; ++t) {
        const float4* src = (const float4*)(g_h + (t & 1) * (Bn * Hn) + bg * 8 * Hn);
        #pragma unroll
        for (int i = 0; i < 4; ++i) {
            int idx = tid + i * 256;
            float4 v = __ldcg(src + idx);
            ((float4*)(h_s + (idx >> 7) * 516))[idx & 127] = v;
        }
        float xp0 = 0.f, xp1 = 0.f, xp2 = 0.f, xp3 = 0.f;
        if (half == 0) {
            const float* xp = ctxproj + ((size_t)b * Sn + t) * Gn + j;
            xp0 = xp[0]; xp1 = xp[512]; xp2 = xp[1024]; xp3 = xp[1536];
        }
        __syncthreads();

        // output-MLP partials for step t-1: warp w -> batch w, E-rows jg*4..+3
        if (t > 0) {
            float padd = 0.f;
            #pragma unroll
            for (int e = 0; e < 4; ++e) {
                float s = 0.f;
                #pragma unroll
                for (int kk = 0; kk < 16; ++kk) {
                    int k = kk * 32 + lane;
                    s += wo1_s[e * 516 + k] * h_s[warp * 516 + k];
                }
                #pragma unroll
                for (int o = 16; o; o >>= 1) s += __shfl_xor_sync(0xffffffffu, s, o);
                padd += fmaxf(s + bo1_r[e], 0.f) * wo2_r[e];
            }
            if (lane == 0)
                atomicAdd(&g_pred[(bg * 8 + warp) * Sn + (t - 1)], padd);
        }

        unsigned long long s0 = 0ull, s1 = 0ull, s2 = 0ull, s3 = 0ull;
        #pragma unroll 8
        for (int kk = 0; kk < 64; ++kk) {
            ulonglong2 h2 = hv[kk]; ulonglong2 w;
            w = w0[kk]; s0 = fma2(h2.x, w.x, s0); s0 = fma2(h2.y, w.y, s0);
            w = w1[kk]; s1 = fma2(h2.x, w.x, s1); s1 = fma2(h2.y, w.y, s1);
            w = w2[kk]; s2 = fma2(h2.x, w.x, s2); s2 = fma2(h2.y, w.y, s2);
            w = w3[kk]; s3 = fma2(h2.x, w.x, s3); s3 = fma2(h2.y, w.y, s3);
        }
        float2 u0 = unpack2(s0), u1 = unpack2(s1), u2 = unpack2(s2), u3 = unpack2(s3);
        float a0 = u0.x + u0.y, a1 = u1.x + u1.y, a2 = u2.x + u2.y, a3 = u3.x + u3.y;

        if (half == 1) {
            float* r = red_s + tl * 4;
            r[0] = a0; r[1] = a1; r[2] = a2; r[3] = a3;
        }
        grp_bar(bg, 2u * (unsigned)t);          // p[t-1] complete; red_s synced

        if (half == 0) {
            float p_prev = (t > 0) ? __ldcg(&g_pred[b * Sn + (t - 1)]) : 0.f;
            const float* r = red_s + tl * 4;
            float gi = a0 + r[0] + xp0 + p_prev * wp_s[0 * 16 + jx];
            float gf = a1 + r[1] + xp1 + p_prev * wp_s[1 * 16 + jx];
            float gg = a2 + r[2] + xp2 + p_prev * wp_s[2 * 16 + jx];
            float go = a3 + r[3] + xp3 + p_prev * wp_s[3 * 16 + jx];
            float si = sigmoidf_(gi), sf = sigmoidf_(gf), so = sigmoidf_(go);
            c_reg = sf * c_reg + si * tanhf(gg);
            float hh = so * tanhf(c_reg);
            __stcg(&g_h[((t + 1) & 1) * (Bn * Hn) + b * Hn + j], hh);
        }
        grp_bar(bg, 2u * (unsigned)t + 1u);
    }

    // final step's output MLP (t = Sn-1)
    {
        const float4* src = (const float4*)(g_h + (Sn & 1) * (Bn * Hn) + bg * 8 * Hn);
        #pragma unroll
        for (int i = 0; i < 4; ++i) {
            int idx = tid + i * 256;
            float4 v = __ldcg(src + idx);
            ((float4*)(h_s + (idx >> 7) * 516))[idx & 127] = v;
        }
        __syncthreads();
        float padd = 0.f;
        #pragma unroll
        for (int e = 0; e < 4; ++e) {
            float s = 0.f;
            #pragma unroll
            for (int kk = 0; kk < 16; ++kk) {
                int k = kk * 32 + lane;
                s += wo1_s[e * 516 + k] * h_s[warp * 516 + k];
            }
            #pragma unroll
            for (int o = 16; o; o >>= 1) s += __shfl_xor_sync(0xffffffffu, s, o);
            padd += fmaxf(s + bo1_r[e], 0.f) * wo2_r[e];
        }
        if (lane == 0)
            atomicAdd(&g_pred[(bg * 8 + warp) * Sn + (Sn - 1)], padd);
    }
}

__global__ void finalize_kernel(const float* __restrict__ mask, float* __restrict__ out)
{
    int i = blockIdx.x * 256 + threadIdx.x;
    if (i < Mn) out[i] = g_pred[i] * mask[i];
}

extern "C" void kernel_launch(void* const* d_in, const int* in_sizes, int n_in,
                              void* d_out, int out_size)
{
    const float* inputs  = (const float*)d_in[0];
    const float* mask    = (const float*)d_in[1];
    const int*   lengths = (const int*)  d_in[2];
    const float* W_e     = (const float*)d_in[3];
    const float* b_e     = (const float*)d_in[4];
    const float* W_a1    = (const float*)d_in[5];
    const float* b_a1    = (const float*)d_in[6];
    const float* W_a2    = (const float*)d_in[7];
    const float* b_a2    = (const float*)d_in[8];
    const float* Wih_e   = (const float*)d_in[9];
    const float* Whh_e   = (const float*)d_in[10];
    const float* bih_e   = (const float*)d_in[11];
    const float* bhh_e   = (const float*)d_in[12];
    const float* enc_h0  = (const float*)d_in[13];
    const float* enc_c0  = (const float*)d_in[14];
    const float* Wih_d   = (const float*)d_in[15];
    const float* Whh_d   = (const float*)d_in[16];
    const float* bih_d   = (const float*)d_in[17];
    const float* bhh_d   = (const float*)d_in[18];
    const float* dec_h0  = (const float*)d_in[19];
    const float* dec_c0  = (const float*)d_in[20];
    const float* W_o1    = (const float*)d_in[21];
    const float* b_o1    = (const float*)d_in[22];
    const float* W_o2    = (const float*)d_in[23];
    const float* b_o2    = (const float*)d_in[24];
    float* out = (float*)d_out;

    float *p_embed, *p_a1, *p_a, *p_attn, *p_xproj, *p_enc, *p_ctx;
    cudaGetSymbolAddress((void**)&p_embed, g_embed);
    cudaGetSymbolAddress((void**)&p_a1,    g_a1);
    cudaGetSymbolAddress((void**)&p_a,     g_a);
    cudaGetSymbolAddress((void**)&p_attn,  g_attn);
    cudaGetSymbolAddress((void**)&p_xproj, g_xproj);
    cudaGetSymbolAddress((void**)&p_enc,   g_enc);
    cudaGetSymbolAddress((void**)&p_ctx,   g_ctx);

    cudaFuncSetAttribute(lstm_enc_kernel, cudaFuncAttributeMaxDynamicSharedMemorySize, ENC_SMEM);
    cudaFuncSetAttribute(lstm_dec_kernel, cudaFuncAttributeMaxDynamicSharedMemorySize, DEC_SMEM);

    sgemm_kernel<<<dim3(En / 128, Mn / 128), 256>>>(
        inputs, W_e, p_embed, Mn, En, 1024, 1024, 1024, 0, b_e, nullptr, 1);
    sgemm_kernel<<<dim3(En / 128, Mn / 128), 256>>>(
        p_embed, W_a1, p_a1, Mn, En, En, En, En, 0, b_a1, nullptr, 1);
    attn_logits_kernel<<<Mn / 8, 256>>>(p_a1, W_a2, b_a2, p_a);
    softmax_time_kernel<<<Bn * 3, 256>>>(p_a, p_attn);
    sgemm_kernel<<<dim3(Gn / 128, Mn / 128), 256>>>(
        p_embed, Wih_e, p_xproj, Mn, Gn, En, En, En, 0, bih_e, bhh_e, 0);
    init_enc_kernel<<<(Bn * Hn + 255) / 256, 256>>>(enc_h0);
    lstm_enc_kernel<<<NBG * NJG, 256, ENC_SMEM>>>(p_xproj, Whh_e, enc_c0, lengths, p_enc);
    context_kernel<<<Mn, Hn / 4>>>(p_attn, p_enc, p_ctx);
    sgemm_kernel<<<dim3(Gn / 128, Mn / 128), 256>>>(
        p_ctx, Wih_d, p_xproj, Mn, Gn, Hn, Hn, Hn + 1, 1, bih_d, bhh_d, 0);
    init_dec_kernel<<<(Mn + 255) / 256, 256>>>(dec_h0, b_o2);
    lstm_dec_kernel<<<NBG * NJG, 256, DEC_SMEM>>>(p_xproj, Whh_d, Wih_d, dec_c0, W_o1, b_o1, W_o2);
    finalize_kernel<<<(Mn + 255) / 256, 256>>>(mask, out);
}

// round 7
// speedup vs baseline: 1.5787x; 1.3861x over previous
#include <cuda_runtime.h>
#include <math.h>

#define Bn   32
#define Sn   1024
#define En   128
#define Hn   512
#define Gn   2048
#define Mn   32768
#define NBG  4      // batch groups (8 batches each)
#define NJG  32     // j groups (16 hidden units each)
#define GRP  32     // blocks per batch group

#define W_PAD   518
#define H_PAD   520
#define RED_PAD 33

__device__ float g_embed[Mn * En];
__device__ float g_a1[Mn * En];
__device__ float g_a[Mn * 3];
__device__ float g_attn[Mn * 3];
__device__ float g_xproj[(size_t)Mn * Gn];
__device__ float g_enc[(size_t)Mn * Hn];
__device__ float g_ctx[(size_t)Mn * Hn];
__device__ float g_pred[Mn];
__device__ float g_h[2 * Bn * Hn];
__device__ unsigned g_cnt[NBG * 32];
__device__ unsigned g_rel[NBG * 32];

// ---- packed f32x2 helpers ----
__device__ __forceinline__ unsigned long long fma2(unsigned long long a,
                                                   unsigned long long b,
                                                   unsigned long long c) {
    unsigned long long d;
    asm("fma.rn.f32x2 %0, %1, %2, %3;" : "=l"(d) : "l"(a), "l"(b), "l"(c));
    return d;
}
__device__ __forceinline__ float2 unpack2(unsigned long long v) {
    float2 r; asm("mov.b64 {%0,%1}, %2;" : "=f"(r.x), "=f"(r.y) : "l"(v)); return r;
}
__device__ __forceinline__ unsigned long long pack2(float lo, float hi) {
    unsigned long long v; asm("mov.b64 %0, {%1,%2};" : "=l"(v) : "f"(lo), "f"(hi)); return v;
}

// ---- per-group acquire/release barrier (GRP arrivals) ----
__device__ __forceinline__ void grp_bar(int g, unsigned phase) {
    __syncthreads();
    if (threadIdx.x == 0) {
        unsigned v;
        asm volatile("atom.acq_rel.gpu.add.u32 %0, [%1], %2;"
                     : "=r"(v) : "l"(&g_cnt[g * 32]), "r"(1u) : "memory");
        if (v == phase * (unsigned)GRP + (unsigned)(GRP - 1)) {
            asm volatile("st.release.gpu.u32 [%0], %1;"
                         :: "l"(&g_rel[g * 32]), "r"(phase + 1u) : "memory");
        } else {
            unsigned r;
            do {
                asm volatile("ld.acquire.gpu.u32 %0, [%1];"
                             : "=r"(r) : "l"(&g_rel[g * 32]) : "memory");
            } while (r < phase + 1u);
        }
    }
    __syncthreads();
}

__device__ __forceinline__ float sigmoidf_(float x) { return 1.0f / (1.0f + expf(-x)); }

// ---------------------------------------------------------------------------
// SIMT SGEMM with packed f32x2 FMA (unchanged)
// ---------------------------------------------------------------------------
__global__ void __launch_bounds__(256) sgemm_kernel(
    const float* __restrict__ A, const float* __restrict__ B, float* __restrict__ C,
    int M, int N, int K, int lda, int ldb, int koff,
    const float* __restrict__ bias1, const float* __restrict__ bias2, int relu)
{
    __shared__ float As[8][128];
    __shared__ float Bs[8][128];
    const int tid = threadIdx.x, bx = blockIdx.x, by = blockIdx.y;
    const int tx = tid & 15, ty = tid >> 4;
    const int arow = tid >> 1, acol = (tid & 1) * 4;
    const float* Ag = A + (size_t)(by * 128 + arow) * lda + acol;
    const float* Bg = B + (size_t)(bx * 128 + arow) * ldb + koff + acol;

    unsigned long long acc2[8][4];
    #pragma unroll
    for (int i = 0; i < 8; ++i)
        #pragma unroll
        for (int j = 0; j < 4; ++j) acc2[i][j] = 0ull;

    for (int k0 = 0; k0 < K; k0 += 8) {
        float4 av = *(const float4*)(Ag + k0);
        float b0 = Bg[k0], b1 = Bg[k0 + 1], b2 = Bg[k0 + 2], b3 = Bg[k0 + 3];
        As[acol + 0][arow] = av.x; As[acol + 1][arow] = av.y;
        As[acol + 2][arow] = av.z; As[acol + 3][arow] = av.w;
        Bs[acol + 0][arow] = b0;   Bs[acol + 1][arow] = b1;
        Bs[acol + 2][arow] = b2;   Bs[acol + 3][arow] = b3;
        __syncthreads();
        #pragma unroll
        for (int kk = 0; kk < 8; ++kk) {
            float4 ra0 = *(const float4*)&As[kk][ty * 8];
            float4 ra1 = *(const float4*)&As[kk][ty * 8 + 4];
            ulonglong2 rb0 = *(const ulonglong2*)&Bs[kk][tx * 8];
            ulonglong2 rb1 = *(const ulonglong2*)&Bs[kk][tx * 8 + 4];
            float ra[8] = {ra0.x, ra0.y, ra0.z, ra0.w, ra1.x, ra1.y, ra1.z, ra1.w};
            #pragma unroll
            for (int i = 0; i < 8; ++i) {
                unsigned long long ap = pack2(ra[i], ra[i]);
                acc2[i][0] = fma2(ap, rb0.x, acc2[i][0]);
                acc2[i][1] = fma2(ap, rb0.y, acc2[i][1]);
                acc2[i][2] = fma2(ap, rb1.x, acc2[i][2]);
                acc2[i][3] = fma2(ap, rb1.y, acc2[i][3]);
            }
        }
        __syncthreads();
    }
    #pragma unroll
    for (int i = 0; i < 8; ++i) {
        int m = by * 128 + ty * 8 + i;
        #pragma unroll
        for (int jp = 0; jp < 4; ++jp) {
            float2 v = unpack2(acc2[i][jp]);
            int n = bx * 128 + tx * 8 + jp * 2;
            float v0 = v.x, v1 = v.y;
            if (bias1) { v0 += bias1[n]; v1 += bias1[n + 1]; }
            if (bias2) { v0 += bias2[n]; v1 += bias2[n + 1]; }
            if (relu)  { v0 = fmaxf(v0, 0.f); v1 = fmaxf(v1, 0.f); }
            C[(size_t)m * N + n]     = v0;
            C[(size_t)m * N + n + 1] = v1;
        }
    }
}

__global__ void attn_logits_kernel(const float* __restrict__ a1,
                                   const float* __restrict__ W_a2,
                                   const float* __restrict__ b_a2,
                                   float* __restrict__ a)
{
    int gw = (blockIdx.x * blockDim.x + threadIdx.x) >> 5;
    int lane = threadIdx.x & 31;
    if (gw >= Mn) return;
    float4 v = ((const float4*)(a1 + (size_t)gw * En))[lane];
    #pragma unroll
    for (int l = 0; l < 3; ++l) {
        float4 wv = ((const float4*)(W_a2 + l * En))[lane];
        float s = v.x * wv.x + v.y * wv.y + v.z * wv.z + v.w * wv.w;
        #pragma unroll
        for (int o = 16; o; o >>= 1) s += __shfl_xor_sync(0xffffffffu, s, o);
        if (lane == 0) a[(size_t)gw * 3 + l] = s + b_a2[l];
    }
}

__global__ void softmax_time_kernel(const float* __restrict__ a, float* __restrict__ attn)
{
    __shared__ float red[256];
    int b = blockIdx.x / 3, l = blockIdx.x - b * 3;
    const float* base = a + (size_t)b * Sn * 3 + l;
    float mx = -3.4e38f;
    for (int s = threadIdx.x; s < Sn; s += 256) mx = fmaxf(mx, base[(size_t)s * 3]);
    red[threadIdx.x] = mx; __syncthreads();
    for (int o = 128; o; o >>= 1) {
        if (threadIdx.x < o) red[threadIdx.x] = fmaxf(red[threadIdx.x], red[threadIdx.x + o]);
        __syncthreads();
    }
    mx = red[0]; __syncthreads();
    float sum = 0.f;
    for (int s = threadIdx.x; s < Sn; s += 256) sum += expf(base[(size_t)s * 3] - mx);
    red[threadIdx.x] = sum; __syncthreads();
    for (int o = 128; o; o >>= 1) {
        if (threadIdx.x < o) red[threadIdx.x] += red[threadIdx.x + o];
        __syncthreads();
    }
    float inv = 1.f / red[0];
    float* ob = attn + (size_t)b * Sn * 3 + l;
    for (int s = threadIdx.x; s < Sn; s += 256)
        ob[(size_t)s * 3] = expf(base[(size_t)s * 3] - mx) * inv;
}

__global__ void context_kernel(const float* __restrict__ attn,
                               const float* __restrict__ enc,
                               float* __restrict__ ctx)
{
    int m = blockIdx.x;
    int t = m & (Sn - 1);
    float a0 = attn[(size_t)m * 3 + 0];
    float a1 = attn[(size_t)m * 3 + 1];
    float a2 = attn[(size_t)m * 3 + 2];
    float4 e0 = ((const float4*)(enc + (size_t)m * Hn))[threadIdx.x];
    float4 r; r.x = a0 * e0.x; r.y = a0 * e0.y; r.z = a0 * e0.z; r.w = a0 * e0.w;
    if (t >= 1) {
        float4 e1 = ((const float4*)(enc + (size_t)(m - 1) * Hn))[threadIdx.x];
        r.x += a1 * e1.x; r.y += a1 * e1.y; r.z += a1 * e1.z; r.w += a1 * e1.w;
    }
    if (t >= 2) {
        float4 e2 = ((const float4*)(enc + (size_t)(m - 2) * Hn))[threadIdx.x];
        r.x += a2 * e2.x; r.y += a2 * e2.y; r.z += a2 * e2.z; r.w += a2 * e2.w;
    }
    ((float4*)(ctx + (size_t)m * Hn))[threadIdx.x] = r;
}

__global__ void init_enc_kernel(const float* __restrict__ h0)
{
    int i = blockIdx.x * 256 + threadIdx.x;
    if (i < Bn * Hn) g_h[i] = h0[i & (Hn - 1)];
    if (i < NBG * 32) { g_cnt[i] = 0u; g_rel[i] = 0u; }
}

__global__ void init_dec_kernel(const float* __restrict__ h0, const float* __restrict__ b_o2)
{
    int i = blockIdx.x * 256 + threadIdx.x;
    if (i < Bn * Hn) g_h[i] = h0[i & (Hn - 1)];
    if (i < Mn) g_pred[i] = b_o2[0];
    if (i < NBG * 32) { g_cnt[i] = 0u; g_rel[i] = 0u; }
}

// ===========================================================================
// Encoder LSTM: 128 blocks = 4 bg x 32 jg. Register-tiled recurrent matmul:
// thread (mj, mkc) computes 4 gates x 8 batches over k-slice [mkc*32, +32).
// smem: w[64][518], h[8][520], red[256][33]
// ===========================================================================
#define ENC_SMEM ((64 * W_PAD + 8 * H_PAD + 256 * RED_PAD) * 4)
__global__ void __launch_bounds__(256, 1) lstm_enc_kernel(
    const float* __restrict__ xproj, const float* __restrict__ Whh,
    const float* __restrict__ c0, const int* __restrict__ lengths,
    float* __restrict__ enc_out)
{
    extern __shared__ float sm[];
    float* w_s   = sm;                         // [64][W_PAD]
    float* h_s   = sm + 64 * W_PAD;            // [8][H_PAD]
    float* red_s = h_s + 8 * H_PAD;            // [256][RED_PAD]

    const int bg = blockIdx.x & 3, jg = blockIdx.x >> 2;
    const int tid = threadIdx.x;
    const int mj = tid & 15, mkc = tid >> 4;   // matmul role
    const int cb = tid >> 4, cj = tid & 15;    // consumer role (tid<128): cb 0..7
    const bool is_cons = (tid < 128);
    const int b = bg * 8 + cb;
    const int j = jg * 16 + cj;

    for (int i = tid; i < 64 * 512; i += 256) {
        int lr = i >> 9, k = i & 511;
        w_s[lr * W_PAD + k] = Whh[(size_t)((lr >> 4) * Hn + jg * 16 + (lr & 15)) * Hn + k];
    }
    float c_reg = is_cons ? c0[j] : 0.f;
    const int len_b = is_cons ? lengths[b] : 0;
    __syncthreads();

    const float* w0p = w_s + (0 * 16 + mj) * W_PAD + mkc * 32;
    const float* w1p = w_s + (1 * 16 + mj) * W_PAD + mkc * 32;
    const float* w2p = w_s + (2 * 16 + mj) * W_PAD + mkc * 32;
    const float* w3p = w_s + (3 * 16 + mj) * W_PAD + mkc * 32;
    const float* hb  = h_s + mkc * 32;

    for (int t = 0; t < Sn; ++t) {
        const float4* src = (const float4*)(g_h + (t & 1) * (Bn * Hn) + bg * 8 * Hn);
        #pragma unroll
        for (int i = 0; i < 4; ++i) {
            int idx = tid + i * 256;
            float4 v = __ldcg(src + idx);
            ((float4*)(h_s + (idx >> 7) * H_PAD))[idx & 127] = v;
        }
        float xp0 = 0.f, xp1 = 0.f, xp2 = 0.f, xp3 = 0.f;
        if (is_cons) {
            const float* xp = xproj + ((size_t)b * Sn + t) * Gn + j;
            xp0 = xp[0]; xp1 = xp[512]; xp2 = xp[1024]; xp3 = xp[1536];
        }
        __syncthreads();

        unsigned long long acc[4][8];
        #pragma unroll
        for (int g = 0; g < 4; ++g)
            #pragma unroll
            for (int bb = 0; bb < 8; ++bb) acc[g][bb] = 0ull;

        #pragma unroll 4
        for (int it = 0; it < 16; ++it) {
            unsigned long long wv0 = *(const unsigned long long*)(w0p + it * 2);
            unsigned long long wv1 = *(const unsigned long long*)(w1p + it * 2);
            unsigned long long wv2 = *(const unsigned long long*)(w2p + it * 2);
            unsigned long long wv3 = *(const unsigned long long*)(w3p + it * 2);
            unsigned long long hv[8];
            #pragma unroll
            for (int bb = 0; bb < 8; ++bb)
                hv[bb] = *(const unsigned long long*)(hb + bb * H_PAD + it * 2);
            #pragma unroll
            for (int bb = 0; bb < 8; ++bb) {
                acc[0][bb] = fma2(wv0, hv[bb], acc[0][bb]);
                acc[1][bb] = fma2(wv1, hv[bb], acc[1][bb]);
                acc[2][bb] = fma2(wv2, hv[bb], acc[2][bb]);
                acc[3][bb] = fma2(wv3, hv[bb], acc[3][bb]);
            }
        }
        float* r = red_s + tid * RED_PAD;
        #pragma unroll
        for (int g = 0; g < 4; ++g)
            #pragma unroll
            for (int bb = 0; bb < 8; ++bb) {
                float2 u = unpack2(acc[g][bb]);
                r[g * 8 + bb] = u.x + u.y;
            }
        __syncthreads();

        if (is_cons) {
            float gi = xp0, gf = xp1, gg = xp2, go = xp3;
            #pragma unroll
            for (int kc = 0; kc < 16; ++kc) {
                const float* rr = red_s + (kc * 16 + cj) * RED_PAD + cb;
                gi += rr[0]; gf += rr[8]; gg += rr[16]; go += rr[24];
            }
            float si = sigmoidf_(gi), sf = sigmoidf_(gf), so = sigmoidf_(go);
            c_reg = sf * c_reg + si * tanhf(gg);
            float hh = so * tanhf(c_reg);
            __stcg(&g_h[((t + 1) & 1) * (Bn * Hn) + b * Hn + j], hh);
            enc_out[((size_t)b * Sn + t) * Hn + j] = (t < len_b) ? hh : 0.f;
        }
        grp_bar(bg, (unsigned)t);
    }
}

// ===========================================================================
// Decoder LSTM: same tiling + scalar feedback p + output MLP.
// ===========================================================================
#define DEC_SMEM ((64 * W_PAD + 8 * H_PAD + 256 * RED_PAD + 4 * 516 + 64) * 4)
__global__ void __launch_bounds__(256, 1) lstm_dec_kernel(
    const float* __restrict__ ctxproj, const float* __restrict__ Whh,
    const float* __restrict__ Wih, const float* __restrict__ c0,
    const float* __restrict__ W_o1, const float* __restrict__ b_o1,
    const float* __restrict__ W_o2)
{
    extern __shared__ float sm[];
    float* w_s   = sm;                         // [64][W_PAD]
    float* h_s   = sm + 64 * W_PAD;            // [8][H_PAD]
    float* red_s = h_s + 8 * H_PAD;            // [256][RED_PAD]
    float* wo1_s = red_s + 256 * RED_PAD;      // [4][516]
    float* wp_s  = wo1_s + 4 * 516;            // [64]

    const int bg = blockIdx.x & 3, jg = blockIdx.x >> 2;
    const int tid = threadIdx.x;
    const int mj = tid & 15, mkc = tid >> 4;
    const int cb = tid >> 4, cj = tid & 15;
    const bool is_cons = (tid < 128);
    const int b = bg * 8 + cb;
    const int j = jg * 16 + cj;
    const int warp = tid >> 5, lane = tid & 31;

    for (int i = tid; i < 64 * 512; i += 256) {
        int lr = i >> 9, k = i & 511;
        w_s[lr * W_PAD + k] = Whh[(size_t)((lr >> 4) * Hn + jg * 16 + (lr & 15)) * Hn + k];
    }
    for (int i = tid; i < 4 * 512; i += 256) {
        int e = i >> 9, k = i & 511;
        wo1_s[e * 516 + k] = W_o1[(size_t)(jg * 4 + e) * Hn + k];
    }
    if (tid < 64) {
        wp_s[tid] = Wih[(size_t)((tid >> 4) * Hn + jg * 16 + (tid & 15)) * 513];
    }
    float wo2_r[4], bo1_r[4];
    #pragma unroll
    for (int e = 0; e < 4; ++e) { wo2_r[e] = W_o2[jg * 4 + e]; bo1_r[e] = b_o1[jg * 4 + e]; }
    float c_reg = is_cons ? c0[j] : 0.f;
    __syncthreads();

    const float* w0p = w_s + (0 * 16 + mj) * W_PAD + mkc * 32;
    const float* w1p = w_s + (1 * 16 + mj) * W_PAD + mkc * 32;
    const float* w2p = w_s + (2 * 16 + mj) * W_PAD + mkc * 32;
    const float* w3p = w_s + (3 * 16 + mj) * W_PAD + mkc * 32;
    const float* hb  = h_s + mkc * 32;

    for (int t = 0; t < Sn; ++t) {
        const float4* src = (const float4*)(g_h + (t & 1) * (Bn * Hn) + bg * 8 * Hn);
        #pragma unroll
        for (int i = 0; i < 4; ++i) {
            int idx = tid + i * 256;
            float4 v = __ldcg(src + idx);
            ((float4*)(h_s + (idx >> 7) * H_PAD))[idx & 127] = v;
        }
        float xp0 = 0.f, xp1 = 0.f, xp2 = 0.f, xp3 = 0.f;
        if (is_cons) {
            const float* xp = ctxproj + ((size_t)b * Sn + t) * Gn + j;
            xp0 = xp[0]; xp1 = xp[512]; xp2 = xp[1024]; xp3 = xp[1536];
        }
        __syncthreads();

        // output-MLP partials for step t-1: warp w -> batch w, E-rows jg*4..+3
        if (t > 0) {
            float padd = 0.f;
            #pragma unroll
            for (int e = 0; e < 4; ++e) {
                float s = 0.f;
                #pragma unroll
                for (int kk = 0; kk < 16; ++kk) {
                    int k = kk * 32 + lane;
                    s += wo1_s[e * 516 + k] * h_s[warp * H_PAD + k];
                }
                #pragma unroll
                for (int o = 16; o; o >>= 1) s += __shfl_xor_sync(0xffffffffu, s, o);
                padd += fmaxf(s + bo1_r[e], 0.f) * wo2_r[e];
            }
            if (lane == 0)
                atomicAdd(&g_pred[(bg * 8 + warp) * Sn + (t - 1)], padd);
        }

        unsigned long long acc[4][8];
        #pragma unroll
        for (int g = 0; g < 4; ++g)
            #pragma unroll
            for (int bb = 0; bb < 8; ++bb) acc[g][bb] = 0ull;

        #pragma unroll 4
        for (int it = 0; it < 16; ++it) {
            unsigned long long wv0 = *(const unsigned long long*)(w0p + it * 2);
            unsigned long long wv1 = *(const unsigned long long*)(w1p + it * 2);
            unsigned long long wv2 = *(const unsigned long long*)(w2p + it * 2);
            unsigned long long wv3 = *(const unsigned long long*)(w3p + it * 2);
            unsigned long long hv[8];
            #pragma unroll
            for (int bb = 0; bb < 8; ++bb)
                hv[bb] = *(const unsigned long long*)(hb + bb * H_PAD + it * 2);
            #pragma unroll
            for (int bb = 0; bb < 8; ++bb) {
                acc[0][bb] = fma2(wv0, hv[bb], acc[0][bb]);
                acc[1][bb] = fma2(wv1, hv[bb], acc[1][bb]);
                acc[2][bb] = fma2(wv2, hv[bb], acc[2][bb]);
                acc[3][bb] = fma2(wv3, hv[bb], acc[3][bb]);
            }
        }
        float* r = red_s + tid * RED_PAD;
        #pragma unroll
        for (int g = 0; g < 4; ++g)
            #pragma unroll
            for (int bb = 0; bb < 8; ++bb) {
                float2 u = unpack2(acc[g][bb]);
                r[g * 8 + bb] = u.x + u.y;
            }
        grp_bar(bg, 2u * (unsigned)t);   // p[t-1] complete everywhere; red_s synced

        if (is_cons) {
            float p_prev = (t > 0) ? __ldcg(&g_pred[b * Sn + (t - 1)]) : 0.f;
            float gi = xp0 + p_prev * wp_s[0 * 16 + cj];
            float gf = xp1 + p_prev * wp_s[1 * 16 + cj];
            float gg = xp2 + p_prev * wp_s[2 * 16 + cj];
            float go = xp3 + p_prev * wp_s[3 * 16 + cj];
            #pragma unroll
            for (int kc = 0; kc < 16; ++kc) {
                const float* rr = red_s + (kc * 16 + cj) * RED_PAD + cb;
                gi += rr[0]; gf += rr[8]; gg += rr[16]; go += rr[24];
            }
            float si = sigmoidf_(gi), sf = sigmoidf_(gf), so = sigmoidf_(go);
            c_reg = sf * c_reg + si * tanhf(gg);
            float hh = so * tanhf(c_reg);
            __stcg(&g_h[((t + 1) & 1) * (Bn * Hn) + b * Hn + j], hh);
        }
        grp_bar(bg, 2u * (unsigned)t + 1u);
    }

    // final step's output MLP (t = Sn-1)
    {
        const float4* src = (const float4*)(g_h + (Sn & 1) * (Bn * Hn) + bg * 8 * Hn);
        #pragma unroll
        for (int i = 0; i < 4; ++i) {
            int idx = tid + i * 256;
            float4 v = __ldcg(src + idx);
            ((float4*)(h_s + (idx >> 7) * H_PAD))[idx & 127] = v;
        }
        __syncthreads();
        float padd = 0.f;
        #pragma unroll
        for (int e = 0; e < 4; ++e) {
            float s = 0.f;
            #pragma unroll
            for (int kk = 0; kk < 16; ++kk) {
                int k = kk * 32 + lane;
                s += wo1_s[e * 516 + k] * h_s[warp * H_PAD + k];
            }
            #pragma unroll
            for (int o = 16; o; o >>= 1) s += __shfl_xor_sync(0xffffffffu, s, o);
            padd += fmaxf(s + bo1_r[e], 0.f) * wo2_r[e];
        }
        if (lane == 0)
            atomicAdd(&g_pred[(bg * 8 + warp) * Sn + (Sn - 1)], padd);
    }
}

__global__ void finalize_kernel(const float* __restrict__ mask, float* __restrict__ out)
{
    int i = blockIdx.x * 256 + threadIdx.x;
    if (i < Mn) out[i] = g_pred[i] * mask[i];
}

extern "C" void kernel_launch(void* const* d_in, const int* in_sizes, int n_in,
                              void* d_out, int out_size)
{
    const float* inputs  = (const float*)d_in[0];
    const float* mask    = (const float*)d_in[1];
    const int*   lengths = (const int*)  d_in[2];
    const float* W_e     = (const float*)d_in[3];
    const float* b_e     = (const float*)d_in[4];
    const float* W_a1    = (const float*)d_in[5];
    const float* b_a1    = (const float*)d_in[6];
    const float* W_a2    = (const float*)d_in[7];
    const float* b_a2    = (const float*)d_in[8];
    const float* Wih_e   = (const float*)d_in[9];
    const float* Whh_e   = (const float*)d_in[10];
    const float* bih_e   = (const float*)d_in[11];
    const float* bhh_e   = (const float*)d_in[12];
    const float* enc_h0  = (const float*)d_in[13];
    const float* enc_c0  = (const float*)d_in[14];
    const float* Wih_d   = (const float*)d_in[15];
    const float* Whh_d   = (const float*)d_in[16];
    const float* bih_d   = (const float*)d_in[17];
    const float* bhh_d   = (const float*)d_in[18];
    const float* dec_h0  = (const float*)d_in[19];
    const float* dec_c0  = (const float*)d_in[20];
    const float* W_o1    = (const float*)d_in[21];
    const float* b_o1    = (const float*)d_in[22];
    const float* W_o2    = (const float*)d_in[23];
    const float* b_o2    = (const float*)d_in[24];
    float* out = (float*)d_out;

    float *p_embed, *p_a1, *p_a, *p_attn, *p_xproj, *p_enc, *p_ctx;
    cudaGetSymbolAddress((void**)&p_embed, g_embed);
    cudaGetSymbolAddress((void**)&p_a1,    g_a1);
    cudaGetSymbolAddress((void**)&p_a,     g_a);
    cudaGetSymbolAddress((void**)&p_attn,  g_attn);
    cudaGetSymbolAddress((void**)&p_xproj, g_xproj);
    cudaGetSymbolAddress((void**)&p_enc,   g_enc);
    cudaGetSymbolAddress((void**)&p_ctx,   g_ctx);

    cudaFuncSetAttribute(lstm_enc_kernel, cudaFuncAttributeMaxDynamicSharedMemorySize, ENC_SMEM);
    cudaFuncSetAttribute(lstm_dec_kernel, cudaFuncAttributeMaxDynamicSharedMemorySize, DEC_SMEM);

    sgemm_kernel<<<dim3(En / 128, Mn / 128), 256>>>(
        inputs, W_e, p_embed, Mn, En, 1024, 1024, 1024, 0, b_e, nullptr, 1);
    sgemm_kernel<<<dim3(En / 128, Mn / 128), 256>>>(
        p_embed, W_a1, p_a1, Mn, En, En, En, En, 0, b_a1, nullptr, 1);
    attn_logits_kernel<<<Mn / 8, 256>>>(p_a1, W_a2, b_a2, p_a);
    softmax_time_kernel<<<Bn * 3, 256>>>(p_a, p_attn);
    sgemm_kernel<<<dim3(Gn / 128, Mn / 128), 256>>>(
        p_embed, Wih_e, p_xproj, Mn, Gn, En, En, En, 0, bih_e, bhh_e, 0);
    init_enc_kernel<<<(Bn * Hn + 255) / 256, 256>>>(enc_h0);
    lstm_enc_kernel<<<NBG * NJG, 256, ENC_SMEM>>>(p_xproj, Whh_e, enc_c0, lengths, p_enc);
    context_kernel<<<Mn, Hn / 4>>>(p_attn, p_enc, p_ctx);
    sgemm_kernel<<<dim3(Gn / 128, Mn / 128), 256>>>(
        p_ctx, Wih_d, p_xproj, Mn, Gn, Hn, Hn, Hn + 1, 1, bih_d, bhh_d, 0);
    init_dec_kernel<<<(Mn + 255) / 256, 256>>>(dec_h0, b_o2);
    lstm_dec_kernel<<<NBG * NJG, 256, DEC_SMEM>>>(p_xproj, Whh_d, Wih_d, dec_c0, W_o1, b_o1, W_o2);
    finalize_kernel<<<(Mn + 255) / 256, 256>>>(mask, out);
}